// round 10
// baseline (speedup 1.0000x reference)
#include <cuda_runtime.h>
#include <cuda_bf16.h>
#include <math.h>
#include <stdint.h>

#define BQ 4
#define PP 1024
#define DDA 1024
#define DDC 3072
#define HID 512
typedef __nv_bfloat16 bf16;

// amax slots
#define AM_ACT 0
#define AM_COMP 1
#define AM_W1A 2
#define AM_W2A 3
#define AM_W1C 4
#define AM_W2C 5
#define AM_ADJ 6
#define AM_T1A 7
#define AM_T2A 8
#define AM_T3A 9
#define AM_T1C 10
#define AM_T2C 11
#define AM_T3C 12

// ---------------- scratch ----------------
__device__ float g_acos[(size_t)BQ*PP*PP];
__device__ float g_ccos[(size_t)BQ*PP*PP];
__device__ float g_na[BQ*PP];
__device__ float g_nc[BQ*PP];
__device__ bf16 g_ah[(size_t)BQ*PP*DDA], g_al[(size_t)BQ*PP*DDA];
__device__ bf16 g_ch[(size_t)BQ*PP*DDC], g_cl[(size_t)BQ*PP*DDC];
__device__ bf16 g_ofah[(size_t)BQ*PP*DDA], g_ofal[(size_t)BQ*PP*DDA];
__device__ bf16 g_ofch[(size_t)BQ*PP*DDC], g_ofcl[(size_t)BQ*PP*DDC];
__device__ bf16 g_wp1h[DDA*128], g_wp1l[DDA*128];
__device__ bf16 g_wp2h[DDC*128], g_wp2l[DDC*128];
__device__ float g_hp1[(size_t)8*BQ*PP*128];
__device__ float g_hp2[(size_t)8*BQ*PP*128];
__device__ char g_xqa1[(size_t)BQ*PP*DDA], g_xqa2[(size_t)BQ*PP*DDA];
__device__ char g_xqc1[(size_t)BQ*PP*DDC], g_xqc2[(size_t)BQ*PP*DDC];
__device__ char g_w1aT1[HID*DDA], g_w1aT2[HID*DDA];
__device__ char g_w2aT1[DDA*HID], g_w2aT2[DDA*HID];
__device__ char g_w1cT1[HID*DDC], g_w1cT2[HID*DDC];
__device__ char g_w2cT1[DDC*HID], g_w2cT2[DDC*HID];
__device__ char g_adja1[(size_t)BQ*PP*PP], g_adja2[(size_t)BQ*PP*PP];
__device__ char g_adjc1[(size_t)BQ*PP*PP], g_adjc2[(size_t)BQ*PP*PP];
__device__ char g_t1T1[(size_t)BQ*HID*PP], g_t1T2[(size_t)BQ*HID*PP];
__device__ char g_t2q1[(size_t)BQ*PP*HID], g_t2q2[(size_t)BQ*PP*HID];
__device__ char g_t3T1[(size_t)BQ*DDC*PP], g_t3T2[(size_t)BQ*DDC*PP];
__device__ float g_t1f[(size_t)BQ*PP*HID];
__device__ float g_t2f[(size_t)BQ*PP*HID];
__device__ float g_t3f[(size_t)BQ*PP*DDC];
__device__ unsigned g_amax[16];

// ====================== helpers ======================
__device__ __forceinline__ uint32_t smem_u32(const void* p) {
    uint32_t a;
    asm("{ .reg .u64 t; cvta.to.shared.u64 t, %1; cvt.u32.u64 %0, t; }" : "=r"(a) : "l"(p));
    return a;
}
__device__ __forceinline__ uint32_t pack_bf16x2(float lo_e, float hi_e) {
    uint32_t r;
    asm("cvt.rn.bf16x2.f32 %0, %1, %2;" : "=r"(r) : "f"(hi_e), "f"(lo_e));
    return r;
}
__device__ __forceinline__ void split2(float x, float y, uint32_t& h, uint32_t& l) {
    uint32_t ux = __float_as_uint(x), uy = __float_as_uint(y);
    h = __byte_perm(ux, uy, 0x7632);
    float lx = x - __uint_as_float(ux & 0xFFFF0000u);
    float ly = y - __uint_as_float(uy & 0xFFFF0000u);
    l = pack_bf16x2(lx, ly);
}
__device__ __forceinline__ void ldmx4(uint32_t* r, uint32_t addr) {
    asm volatile("ldmatrix.sync.aligned.m8n8.x4.shared.b16 {%0,%1,%2,%3}, [%4];"
                 : "=r"(r[0]), "=r"(r[1]), "=r"(r[2]), "=r"(r[3]) : "r"(addr));
}
__device__ __forceinline__ void mma_bf16(float* c, const uint32_t* a, const uint32_t* b) {
    asm volatile(
        "mma.sync.aligned.m16n8k16.row.col.f32.bf16.bf16.f32 "
        "{%0,%1,%2,%3}, {%4,%5,%6,%7}, {%8,%9}, {%0,%1,%2,%3};"
        : "+f"(c[0]), "+f"(c[1]), "+f"(c[2]), "+f"(c[3])
        : "r"(a[0]), "r"(a[1]), "r"(a[2]), "r"(a[3]), "r"(b[0]), "r"(b[1]));
}
__device__ __forceinline__ void mma_s8(int* c, const uint32_t* a, const uint32_t* b) {
    asm volatile(
        "mma.sync.aligned.m16n8k32.row.col.s32.s8.s8.s32 "
        "{%0,%1,%2,%3}, {%4,%5,%6,%7}, {%8,%9}, {%0,%1,%2,%3};"
        : "+r"(c[0]), "+r"(c[1]), "+r"(c[2]), "+r"(c[3])
        : "r"(a[0]), "r"(a[1]), "r"(a[2]), "r"(a[3]), "r"(b[0]), "r"(b[1]));
}
__device__ __forceinline__ void cp16(uint32_t dst, const void* src) {
    asm volatile("cp.async.cg.shared.global [%0], [%1], 16;" :: "r"(dst), "l"(src) : "memory");
}
#define CP_COMMIT() asm volatile("cp.async.commit_group;" ::: "memory")

__device__ __forceinline__ uint32_t ksw(int row, int c) {   // bf16 64B rows
    return (uint32_t)(row * 64) + ((uint32_t)(c ^ ((row >> 1) & 3)) << 4);
}
__device__ __forceinline__ uint32_t qsw(int row, int c) {   // int8 32B rows
    return (uint32_t)(row * 32) + ((uint32_t)(c ^ ((row >> 2) & 1)) << 4);
}
__device__ __forceinline__ void quant2(float f, char& q1, char& q2) {
    float r1 = fminf(fmaxf(rintf(f), -127.f), 127.f);
    float r2 = fminf(fmaxf(rintf((f - r1) * 256.f), -127.f), 127.f);
    q1 = (char)(int)r1;
    q2 = (char)(int)r2;
}

// ====================== bf16x3 GEMM (grams + heads; B is [N,K]) ======================
#define ATILE 8192
#define ASTG  16384
#define SBYTES 32768
#define NSTAGE 3
#define GSMEM (NSTAGE*SBYTES)

__global__ __launch_bounds__(256, 2)
void gemmx_k(const bf16* __restrict__ Ah, const bf16* __restrict__ Al,
             const bf16* __restrict__ Bh, const bf16* __restrict__ Bl,
             float* __restrict__ C,
             int N, int K, int Klen, int symm,
             long sA, long sB, long sC, int ldc)
{
    if (!Klen && symm && blockIdx.x < blockIdx.y) return;
    extern __shared__ char sm[];
    uint32_t smb = smem_u32(sm);

    const int tid = threadIdx.x;
    const int lane = tid & 31;
    const int wid = tid >> 5;
    const int wm = (wid >> 2) * 64;
    const int wn = (wid & 3) * 32;

    long bz = blockIdx.z;
    const int bm = blockIdx.y * 128;
    const int nxt = N >> 7;
    int bn, kbase, kslice = 0;
    if (Klen) {
        kslice = (int)blockIdx.x / nxt;
        bn = ((int)blockIdx.x - kslice * nxt) << 7;
        kbase = kslice * Klen;
    } else {
        bn = (int)blockIdx.x << 7;
        kbase = 0;
    }
    const int KL = Klen ? Klen : K;

    const bf16* Ahb = Ah + bz * sA + (size_t)bm * K + kbase;
    const bf16* Alb = Al + bz * sA + (size_t)bm * K + kbase;
    const bf16* Bhb = Bh + bz * sB + (size_t)bn * K + kbase;
    const bf16* Blb = Bl + bz * sB + (size_t)bn * K + kbase;
    float* Cb = Klen ? C + (size_t)kslice * sC : C + bz * sC;

    float acc[4][4][4];
#pragma unroll
    for (int i = 0; i < 4; i++)
#pragma unroll
        for (int j = 0; j < 4; j++)
#pragma unroll
            for (int r = 0; r < 4; r++) acc[i][j][r] = 0.f;

    const int nch = KL >> 5;

    auto load_stage = [&](int kt, int s) {
        uint32_t base = smb + (uint32_t)s * SBYTES;
        int k0 = kt << 5;
#pragma unroll
        for (int it = 0; it < 4; it++) {
            int id = it * 256 + tid;
            int hl = id >> 9, rid = id & 511;
            int row = rid >> 2, c = rid & 3;
            cp16(base + hl * ATILE + ksw(row, c),
                 (hl ? Alb : Ahb) + (size_t)row * K + k0 + c * 8);
        }
#pragma unroll
        for (int it = 0; it < 4; it++) {
            int id = it * 256 + tid;
            int hl = id >> 9, rid = id & 511;
            int row = rid >> 2, c = rid & 3;
            cp16(base + ASTG + hl * ATILE + ksw(row, c),
                 (hl ? Blb : Bhb) + (size_t)row * K + k0 + c * 8);
        }
        CP_COMMIT();
    };

    load_stage(0, 0);
    load_stage(1, 1);

    int sc = 0, sl = 2;
    for (int kt = 0; kt < nch; kt++) {
        asm volatile("cp.async.wait_group 1;" ::: "memory");
        __syncthreads();
        if (kt + 2 < nch) {
            load_stage(kt + 2, sl);
            sl = (sl + 1 == NSTAGE) ? 0 : sl + 1;
        } else {
            CP_COMMIT();
        }
        uint32_t aB = smb + (uint32_t)sc * SBYTES;
        uint32_t bB = aB + ASTG;
        sc = (sc + 1 == NSTAGE) ? 0 : sc + 1;

#pragma unroll
        for (int kh = 0; kh < 2; kh++) {
            uint32_t ahi[4][4], alo[4][4];
            {
                int u = kh * 2 + (lane >> 4);
#pragma unroll
                for (int i = 0; i < 4; i++) {
                    int r = wm + (lane & 15) + i * 16;
                    uint32_t ro = ksw(r, u);
                    ldmx4(ahi[i], aB + ro);
                    ldmx4(alo[i], aB + ATILE + ro);
                }
            }
#pragma unroll
            for (int jp = 0; jp < 2; jp++) {
                uint32_t bh2[4], bl2[4];
                int row = wn + jp * 16 + ((lane >> 4) << 3) + (lane & 7);
                int u = kh * 2 + ((lane >> 3) & 1);
                uint32_t ro = ksw(row, u);
                ldmx4(bh2, bB + ro);
                ldmx4(bl2, bB + ATILE + ro);
                int j0 = 2 * jp, j1 = 2 * jp + 1;
#pragma unroll
                for (int i = 0; i < 4; i++) {
                    mma_bf16(acc[i][j0], ahi[i], bh2 + 0);
                    mma_bf16(acc[i][j1], ahi[i], bh2 + 2);
                }
#pragma unroll
                for (int i = 0; i < 4; i++) {
                    mma_bf16(acc[i][j0], ahi[i], bl2 + 0);
                    mma_bf16(acc[i][j1], ahi[i], bl2 + 2);
                }
#pragma unroll
                for (int i = 0; i < 4; i++) {
                    mma_bf16(acc[i][j0], alo[i], bh2 + 0);
                    mma_bf16(acc[i][j1], alo[i], bh2 + 2);
                }
            }
        }
    }

#pragma unroll
    for (int i = 0; i < 4; i++) {
        int r0 = bm + wm + i * 16 + (lane >> 2);
        int r1 = r0 + 8;
#pragma unroll
        for (int j = 0; j < 4; j++) {
            int gc = bn + wn + j * 8 + (lane & 3) * 2;
            *reinterpret_cast<float2*>(Cb + (size_t)r0 * ldc + gc) =
                make_float2(acc[i][j][0], acc[i][j][1]);
            *reinterpret_cast<float2*>(Cb + (size_t)r1 * ldc + gc) =
                make_float2(acc[i][j][2], acc[i][j][3]);
        }
    }
}

// ====================== int8x2 GEMM (GCN chains) ======================
// D = sA*sB*(P + Q/256). A [M,K] q1/q2 row-major, B [N,K] q1/q2 row-major.
// CTA 128x128, 512 thr, 16 warps 4x4 (32x32 warp tile), 4 stages x 16KB.
#define QSTG 16384
#define QNST 4
#define QSMEM (QNST*QSTG)

__global__ __launch_bounds__(512, 1)
void igemm_k(const char* __restrict__ A1, const char* __restrict__ A2,
             const char* __restrict__ B1, const char* __restrict__ B2,
             int N, int K, long sA, long sB, long sC,
             const unsigned* __restrict__ pamA, const unsigned* __restrict__ pamB,
             float* __restrict__ C, bf16* __restrict__ Ch, bf16* __restrict__ Cl,
             int ldc, const float* __restrict__ bias,
             const float* __restrict__ resid, long sR, int relu_flag,
             unsigned* __restrict__ amaxOut)
{
    extern __shared__ char sm[];
    uint32_t smb = smem_u32(sm);
    const int tid = threadIdx.x, lane = tid & 31, wid = tid >> 5;
    const int wm = (wid >> 2) * 32, wn = (wid & 3) * 32;
    long bz = blockIdx.z;
    const int bm = blockIdx.y * 128, bn = blockIdx.x * 128;

    const char* A1b = A1 + bz * sA + (size_t)bm * K;
    const char* A2b = A2 + bz * sA + (size_t)bm * K;
    const char* B1b = B1 + bz * sB + (size_t)bn * K;
    const char* B2b = B2 + bz * sB + (size_t)bn * K;
    float* Cb = C ? C + bz * sC : (float*)0;
    bf16* Chb = Ch ? Ch + bz * sC : (bf16*)0;
    bf16* Clb = Cl ? Cl + bz * sC : (bf16*)0;
    const float* Rb = resid ? resid + bz * sR : (const float*)0;

    int P[2][4][4], Q[2][4][4];
#pragma unroll
    for (int i = 0; i < 2; i++)
#pragma unroll
        for (int j = 0; j < 4; j++)
#pragma unroll
            for (int r = 0; r < 4; r++) { P[i][j][r] = 0; Q[i][j][r] = 0; }

    const int nch = K >> 5;

    auto load_stage = [&](int kt, int s) {
        uint32_t base = smb + (uint32_t)s * QSTG;
        int k0 = kt << 5;
        int q = tid >> 8, rid = tid & 255;
        int row = rid >> 1, c = rid & 1;
        cp16(base + q * 4096 + qsw(row, c),
             (q ? A2b : A1b) + (size_t)row * K + k0 + c * 16);
        cp16(base + 8192 + q * 4096 + qsw(row, c),
             (q ? B2b : B1b) + (size_t)row * K + k0 + c * 16);
        CP_COMMIT();
    };

    load_stage(0, 0);
    load_stage(1, 1);
    load_stage(2, 2);

    int sc = 0, sl = 3;
    for (int kt = 0; kt < nch; kt++) {
        asm volatile("cp.async.wait_group 2;" ::: "memory");
        __syncthreads();
        if (kt + 3 < nch) {
            load_stage(kt + 3, sl);
            sl = (sl + 1 == QNST) ? 0 : sl + 1;
        } else {
            CP_COMMIT();
        }
        uint32_t aB = smb + (uint32_t)sc * QSTG;
        uint32_t bB = aB + 8192;
        sc = (sc + 1 == QNST) ? 0 : sc + 1;

        uint32_t aq1[2][4], aq2[2][4];
        {
            int u = lane >> 4;
#pragma unroll
            for (int i = 0; i < 2; i++) {
                int r = wm + i * 16 + (lane & 15);
                uint32_t ro = qsw(r, u);
                ldmx4(aq1[i], aB + ro);
                ldmx4(aq2[i], aB + 4096 + ro);
            }
        }
#pragma unroll
        for (int jp = 0; jp < 2; jp++) {
            int row = wn + jp * 16 + ((lane >> 4) << 3) + (lane & 7);
            int u = (lane >> 3) & 1;
            uint32_t ro = qsw(row, u);
            uint32_t b1r[4], b2r[4];
            ldmx4(b1r, bB + ro);
            ldmx4(b2r, bB + 4096 + ro);
#pragma unroll
            for (int i = 0; i < 2; i++) {
#pragma unroll
                for (int jj = 0; jj < 2; jj++) {
                    int j = 2 * jp + jj;
                    mma_s8(P[i][j], aq1[i], b1r + 2 * jj);
                    mma_s8(Q[i][j], aq1[i], b2r + 2 * jj);
                    mma_s8(Q[i][j], aq2[i], b1r + 2 * jj);
                }
            }
        }
    }

    float sab = (__uint_as_float(*pamA) * (1.f / 127.f)) *
                (__uint_as_float(*pamB) * (1.f / 127.f));
    float mloc = 0.f;
#pragma unroll
    for (int i = 0; i < 2; i++) {
        int r0 = bm + wm + i * 16 + (lane >> 2);
        int r1 = r0 + 8;
#pragma unroll
        for (int j = 0; j < 4; j++) {
            int gc = bn + wn + j * 8 + (lane & 3) * 2;
            float v[4];
#pragma unroll
            for (int r = 0; r < 4; r++)
                v[r] = sab * ((float)P[i][j][r] + (float)Q[i][j][r] * (1.f / 256.f));
            if (bias) {
                float2 bv = *reinterpret_cast<const float2*>(bias + gc);
                v[0] += bv.x; v[1] += bv.y; v[2] += bv.x; v[3] += bv.y;
            }
            if (Rb) {
                float2 q0 = *reinterpret_cast<const float2*>(Rb + (size_t)r0 * ldc + gc);
                float2 q1 = *reinterpret_cast<const float2*>(Rb + (size_t)r1 * ldc + gc);
                v[0] += q0.x; v[1] += q0.y; v[2] += q1.x; v[3] += q1.y;
            }
            if (relu_flag) {
#pragma unroll
                for (int r = 0; r < 4; r++) v[r] = fmaxf(v[r], 0.f);
            }
            if (Cb) {
                *reinterpret_cast<float2*>(Cb + (size_t)r0 * ldc + gc) = make_float2(v[0], v[1]);
                *reinterpret_cast<float2*>(Cb + (size_t)r1 * ldc + gc) = make_float2(v[2], v[3]);
            }
            if (Chb) {
                uint32_t h0, l0, h1, l1;
                split2(v[0], v[1], h0, l0);
                split2(v[2], v[3], h1, l1);
                *reinterpret_cast<uint32_t*>(Chb + (size_t)r0 * ldc + gc) = h0;
                *reinterpret_cast<uint32_t*>(Clb + (size_t)r0 * ldc + gc) = l0;
                *reinterpret_cast<uint32_t*>(Chb + (size_t)r1 * ldc + gc) = h1;
                *reinterpret_cast<uint32_t*>(Clb + (size_t)r1 * ldc + gc) = l1;
            }
            if (amaxOut) {
#pragma unroll
                for (int r = 0; r < 4; r++) mloc = fmaxf(mloc, fabsf(v[r]));
            }
        }
    }
    if (amaxOut) {
#pragma unroll
        for (int off = 16; off; off >>= 1)
            mloc = fmaxf(mloc, __shfl_xor_sync(0xffffffffu, mloc, off));
        if (lane == 0) atomicMax(amaxOut, __float_as_uint(mloc));
    }
}

// ====================== elementwise / quant kernels ======================
__global__ void initamax_k(unsigned* a)
{
    int i = threadIdx.x;
    if (i < 16) a[i] = (i == AM_ADJ) ? __float_as_uint(2.1f) : 0u;
}

__global__ void absmax_k(const float* __restrict__ x, size_t n4, unsigned* amax)
{
    __shared__ float wmax[8];
    float m = 0.f;
    for (size_t i = (size_t)blockIdx.x * blockDim.x + threadIdx.x; i < n4;
         i += (size_t)gridDim.x * blockDim.x) {
        float4 v = reinterpret_cast<const float4*>(x)[i];
        m = fmaxf(m, fmaxf(fmaxf(fabsf(v.x), fabsf(v.y)), fmaxf(fabsf(v.z), fabsf(v.w))));
    }
#pragma unroll
    for (int off = 16; off; off >>= 1)
        m = fmaxf(m, __shfl_xor_sync(0xffffffffu, m, off));
    int w = threadIdx.x >> 5;
    if ((threadIdx.x & 31) == 0) wmax[w] = m;
    __syncthreads();
    if (threadIdx.x == 0) {
        float t = wmax[0];
        for (int i = 1; i < (int)(blockDim.x >> 5); i++) t = fmaxf(t, wmax[i]);
        atomicMax(amax, __float_as_uint(t));
    }
}

__global__ void quant_k(const float* __restrict__ x, size_t n4,
                        const unsigned* __restrict__ pam,
                        char* __restrict__ q1, char* __restrict__ q2)
{
    float inv = 127.f / fmaxf(__uint_as_float(*pam), 1e-20f);
    for (size_t i = (size_t)blockIdx.x * blockDim.x + threadIdx.x; i < n4;
         i += (size_t)gridDim.x * blockDim.x) {
        float4 v = reinterpret_cast<const float4*>(x)[i];
        char a1[4], a2[4];
        quant2(v.x * inv, a1[0], a2[0]);
        quant2(v.y * inv, a1[1], a2[1]);
        quant2(v.z * inv, a1[2], a2[2]);
        quant2(v.w * inv, a1[3], a2[3]);
        reinterpret_cast<uchar4*>(q1)[i] = *reinterpret_cast<uchar4*>(a1);
        reinterpret_cast<uchar4*>(q2)[i] = *reinterpret_cast<uchar4*>(a2);
    }
}

// X [B][Mb][N] fp32 -> q [B][N][Mb] int8 pair
__global__ __launch_bounds__(256)
void transquant_k(const float* __restrict__ X, int Mb, int N,
                  const unsigned* __restrict__ pam,
                  char* __restrict__ q1, char* __restrict__ q2)
{
    __shared__ float t[32][33];
    float inv = 127.f / fmaxf(__uint_as_float(*pam), 1e-20f);
    int mt = blockIdx.x, nt = blockIdx.y, b = blockIdx.z;
    int tx = threadIdx.x & 31, ty = threadIdx.x >> 5;
    const float* Xb = X + (size_t)b * Mb * N;
#pragma unroll
    for (int it = 0; it < 4; it++) {
        int r = ty + it * 8;
        t[r][tx] = Xb[(size_t)(mt * 32 + r) * N + nt * 32 + tx];
    }
    __syncthreads();
#pragma unroll
    for (int it = 0; it < 4; it++) {
        int r = ty + it * 8;
        char a1, a2;
        quant2(t[tx][r] * inv, a1, a2);
        size_t d = ((size_t)b * N + nt * 32 + r) * Mb + mt * 32 + tx;
        q1[d] = a1;
        q2[d] = a2;
    }
}

__global__ void zero_k(uint4* __restrict__ p, size_t n16)
{
    for (size_t i = (size_t)blockIdx.x * blockDim.x + threadIdx.x; i < n16;
         i += (size_t)gridDim.x * blockDim.x)
        p[i] = make_uint4(0, 0, 0, 0);
}

__global__ void split_k(const float* __restrict__ s, bf16* __restrict__ h,
                        bf16* __restrict__ l, size_t n4)
{
    for (size_t i = (size_t)blockIdx.x * blockDim.x + threadIdx.x; i < n4;
         i += (size_t)gridDim.x * blockDim.x) {
        float4 v = reinterpret_cast<const float4*>(s)[i];
        uint32_t h0, l0, h1, l1;
        split2(v.x, v.y, h0, l0);
        split2(v.z, v.w, h1, l1);
        reinterpret_cast<uint2*>(h)[i] = make_uint2(h0, h1);
        reinterpret_cast<uint2*>(l)[i] = make_uint2(l0, l1);
    }
}

// head weights: src [K][Nsrc] -> padded transposed [(col0+n)][K] bf16 hi/lo
__global__ void padsplitT_k(const float* __restrict__ src, bf16* __restrict__ h,
                            bf16* __restrict__ l, int K, int Nsrc, int col0)
{
    int total = K * Nsrc;
    for (int i = blockIdx.x * blockDim.x + threadIdx.x; i < total;
         i += gridDim.x * blockDim.x) {
        int k = i / Nsrc, n = i - k * Nsrc;
        float v = src[i];
        uint32_t u = __float_as_uint(v);
        float lv = v - __uint_as_float(u & 0xFFFF0000u);
        size_t d = (size_t)(col0 + n) * K + k;
        reinterpret_cast<unsigned short*>(h)[d] = (unsigned short)(u >> 16);
        reinterpret_cast<unsigned short*>(l)[d] = (unsigned short)(pack_bf16x2(lv, lv) & 0xFFFFu);
    }
}

__global__ void norms_k(const float* __restrict__ G, float* __restrict__ nrm)
{
    int i = blockIdx.x * blockDim.x + threadIdx.x;
    if (i < BQ * PP) {
        int b = i >> 10, p = i & (PP - 1);
        nrm[i] = sqrtf(G[((size_t)b * PP + p) * PP + p]);
    }
}

__global__ __launch_bounds__(256)
void mirror_k(float* __restrict__ A, float* __restrict__ B)
{
    int tj = blockIdx.x, ti = blockIdx.y, b = blockIdx.z;
    if (ti <= tj || (ti >> 2) == (tj >> 2)) return;
    __shared__ float ta[32][33], tb[32][33];
    int tx = threadIdx.x & 31, ty = threadIdx.x >> 5;
    size_t base = (size_t)b * PP * PP;
#pragma unroll
    for (int it = 0; it < 4; it++) {
        int r = ty + it * 8;
        size_t src = base + (size_t)(tj * 32 + r) * PP + ti * 32 + tx;
        ta[r][tx] = A[src];
        tb[r][tx] = B[src];
    }
    __syncthreads();
#pragma unroll
    for (int it = 0; it < 4; it++) {
        int r = ty + it * 8;
        size_t dst = base + (size_t)(ti * 32 + r) * PP + tj * 32 + tx;
        A[dst] = ta[tx][r];
        B[dst] = tb[tx][r];
    }
}

__global__ void redheads_k(const float* __restrict__ hp1, const float* __restrict__ hp2,
                           const float* __restrict__ fab, const float* __restrict__ fcb,
                           const float* __restrict__ frb, float* __restrict__ out)
{
    int i = blockIdx.x * blockDim.x + threadIdx.x;
    int total = BQ * PP * 81;
    if (i >= total) return;
    int row = i / 81, col = i - row * 81;
    float v;
    if (col < 21) {
        v = fab[col];
#pragma unroll
        for (int s = 0; s < 8; s++)
            v += hp1[((size_t)s * BQ * PP + row) * 128 + col];
    } else {
        int c2 = col - 21;
        v = (c2 < 20) ? fcb[c2] : frb[c2 - 20];
#pragma unroll
        for (int s = 0; s < 8; s++)
            v += hp2[((size_t)s * BQ * PP + row) * 128 + c2];
    }
    out[i] = v;
}

// ---------------- graph construction (int8 adjacency out, fixed scale 2.1) ----------
__device__ __forceinline__ void warp_argmin(float& v, int& l)
{
#pragma unroll
    for (int off = 16; off; off >>= 1) {
        float ov = __shfl_down_sync(0xffffffffu, v, off);
        int ol = __shfl_down_sync(0xffffffffu, l, off);
        if (ov < v) { v = ov; l = ol; }
    }
    v = __shfl_sync(0xffffffffu, v, 0);
    l = __shfl_sync(0xffffffffu, l, 0);
}
__device__ __forceinline__ void warp_argmax(float& v, int& l)
{
#pragma unroll
    for (int off = 16; off; off >>= 1) {
        float ov = __shfl_down_sync(0xffffffffu, v, off);
        int ol = __shfl_down_sync(0xffffffffu, l, off);
        if (ov > v) { v = ov; l = ol; }
    }
    v = __shfl_sync(0xffffffffu, v, 0);
    l = __shfl_sync(0xffffffffu, l, 0);
}

__global__ __launch_bounds__(128)
void build_adj_k(const float* __restrict__ iou, const float* __restrict__ dis,
                 const float* __restrict__ acos_, const float* __restrict__ ccos_,
                 const float* __restrict__ na, const float* __restrict__ nc,
                 const int* __restrict__ props,
                 char* __restrict__ aq1, char* __restrict__ aq2,
                 char* __restrict__ cq1, char* __restrict__ cq2)
{
    __shared__ float sio[4][PP];
    const float SADJ = 127.f / 2.1f;
    int warp = threadIdx.x >> 5, lane = threadIdx.x & 31;
    int row = blockIdx.x * 4 + warp;
    if (row >= BQ * PP) return;
    int b = row >> 10;
    int p = row & (PP - 1);
    const float* iour = iou + (size_t)row * PP;
    const float* disr = dis + (size_t)row * PP;
    const float* ar = acos_ + (size_t)row * PP;
    const float* cr = ccos_ + (size_t)row * PP;
    const float* nab = na + (b << 10);
    const float* ncb = nc + (b << 10);
    float npa = nab[p], npc = ncb[p];
    int pn = props[b];
    bool pv = p < pn;

    float* io_s = sio[warp];
    for (int q = lane; q < PP; q += 32) io_s[q] = iour[q];
    __syncwarp();

    float dv[6]; int di[6];
#pragma unroll
    for (int j = 0; j < 6; j++) { dv[j] = 3.0e38f; di[j] = -1; }
    float sv[2] = {-3.0e38f, -3.0e38f};
    int si2[2] = {-1, -1};

    for (int q = lane; q < PP; q += 32) {
        float io = io_s[q];
        bool ip = io > 0.0f;
        bool qv = q < pn;
        bool v2 = pv && qv;

        float dm = v2 ? (ip ? 2.0f : disr[q]) : 1.0e9f;
        if (dm < dv[5]) {
            dv[5] = dm; di[5] = q;
#pragma unroll
            for (int j = 5; j > 0; j--) {
                if (dv[j] < dv[j - 1]) {
                    float tv = dv[j]; dv[j] = dv[j - 1]; dv[j - 1] = tv;
                    int ti = di[j]; di[j] = di[j - 1]; di[j - 1] = ti;
                }
            }
        }
        float av = ar[q] / (npa * nab[q] + 1e-6f);
        float sm = v2 ? (ip ? 0.0f : (av - (q == p ? 1.0f : 0.0f))) : -1.0e9f;
        if (sm > sv[1]) {
            if (sm > sv[0]) { sv[1] = sv[0]; si2[1] = si2[0]; sv[0] = sm; si2[0] = q; }
            else            { sv[1] = sm; si2[1] = q; }
        }
    }

    int sel[8];
    {
        int ptr = 0;
        for (int k = 0; k < 6; k++) {
            float cv = (ptr < 6) ? dv[ptr] : 3.0e38f;
            int ci = (ptr < 6) ? di[ptr] : -1;
            float v = cv; int l = lane;
            warp_argmin(v, l);
            sel[k] = __shfl_sync(0xffffffffu, ci, l);
            if (lane == l) ptr++;
        }
    }
    {
        int ptr = 0;
        for (int k = 0; k < 2; k++) {
            float cv = (ptr < 2) ? sv[ptr] : -3.0e38f;
            int ci = (ptr < 2) ? si2[ptr] : -1;
            float v = cv; int l = lane;
            warp_argmax(v, l);
            sel[6 + k] = __shfl_sync(0xffffffffu, ci, l);
            if (lane == l) ptr++;
        }
    }
#pragma unroll
    for (int k = 0; k < 8; k++) {
        int q = sel[k];
        bool ok = (q >= 0) && pv && (q < pn) && !(io_s[q] > 0.0f);
        sel[k] = ok ? q : -1;
    }

    unsigned mbits = 0;
    for (int i = 0; i < 32; i++) {
        int q = lane + 32 * i;
        float io = io_s[q];
        bool bit = (q != p) && (io > 0.7f);
#pragma unroll
        for (int k = 0; k < 8; k++) bit |= (sel[k] == q);
        mbits |= (bit ? 1u : 0u) << i;
    }
    int cnt = __popc(mbits);
#pragma unroll
    for (int off = 16; off; off >>= 1) cnt += __shfl_xor_sync(0xffffffffu, cnt, off);
    float inv = 1.0f / ((float)cnt + 1e-6f);

    char* a1 = aq1 + (size_t)row * PP;
    char* a2 = aq2 + (size_t)row * PP;
    char* c1 = cq1 + (size_t)row * PP;
    char* c2 = cq2 + (size_t)row * PP;
    for (int i = 0; i < 32; i++) {
        int q = lane + 32 * i;
        float m = ((mbits >> i) & 1u) ? inv : 0.0f;
        if (q == p) m += 1.0f;
        float av = ar[q] / (npa * nab[q] + 1e-6f);
        float cv = cr[q] / (npc * ncb[q] + 1e-6f);
        float a = fmaxf(av * m, 0.f) * SADJ;
        float c = fmaxf(cv * m, 0.f) * SADJ;
        char x1, x2, y1, y2;
        quant2(a, x1, x2);
        quant2(c, y1, y2);
        a1[q] = x1; a2[q] = x2;
        c1[q] = y1; c2[q] = y2;
    }
}

// ---------------- host ----------------
static void gb(const bf16* Ah, const bf16* Al, const bf16* Bh, const bf16* Bl,
               float* C, int M, int N, int K, int Klen, int symm,
               long sA, long sB, long sC, int batch, int ldc)
{
    cudaFuncSetAttribute(gemmx_k, cudaFuncAttributeMaxDynamicSharedMemorySize, GSMEM);
    int nxt = N >> 7;
    int gxd = Klen ? nxt * (K / Klen) : nxt;
    dim3 grid(gxd, M / 128, batch);
    gemmx_k<<<grid, 256, GSMEM>>>(Ah, Al, Bh, Bl, C, N, K, Klen, symm, sA, sB, sC, ldc);
}

static void gi(const char* A1, const char* A2, const char* B1, const char* B2,
               int M, int N, int K, long sA, long sB, long sC, int batch,
               const unsigned* pamA, const unsigned* pamB,
               float* C, bf16* Ch, bf16* Cl, int ldc,
               const float* bias, const float* resid, long sR, int relu,
               unsigned* amaxOut)
{
    cudaFuncSetAttribute(igemm_k, cudaFuncAttributeMaxDynamicSharedMemorySize, QSMEM);
    dim3 grid(N / 128, M / 128, batch);
    igemm_k<<<grid, 512, QSMEM>>>(A1, A2, B1, B2, N, K, sA, sB, sC, pamA, pamB,
                                  C, Ch, Cl, ldc, bias, resid, sR, relu, amaxOut);
}

#define SYM(var, sym) cudaGetSymbolAddress((void**)&var, sym)

extern "C" void kernel_launch(void* const* d_in, const int* in_sizes, int n_in,
                              void* d_out, int out_size)
{
    const float* act   = (const float*)d_in[0];
    const float* comp  = (const float*)d_in[1];
    const float* iou   = (const float*)d_in[2];
    const float* dis   = (const float*)d_in[3];
    const int*   props = (const int*)d_in[4];
    const float* a_w1  = (const float*)d_in[5];
    const float* a_b1  = (const float*)d_in[6];
    const float* a_w2  = (const float*)d_in[7];
    const float* a_b2  = (const float*)d_in[8];
    const float* c_w1  = (const float*)d_in[9];
    const float* c_b1  = (const float*)d_in[10];
    const float* c_w2  = (const float*)d_in[11];
    const float* c_b2  = (const float*)d_in[12];
    const float* fa_w  = (const float*)d_in[13];
    const float* fa_b  = (const float*)d_in[14];
    const float* fc_w  = (const float*)d_in[15];
    const float* fc_b  = (const float*)d_in[16];
    const float* fr_w  = (const float*)d_in[17];
    const float* fr_b  = (const float*)d_in[18];
    float* out = (float*)d_out;

    float *acos_, *ccos_, *na, *nc, *hp1, *hp2, *t1f, *t2f, *t3f;
    bf16 *ah, *al, *ch_, *cl_, *ofah, *ofal, *ofch, *ofcl;
    bf16 *wp1h, *wp1l, *wp2h, *wp2l;
    char *xqa1, *xqa2, *xqc1, *xqc2, *w1aT1, *w1aT2, *w2aT1, *w2aT2;
    char *w1cT1, *w1cT2, *w2cT1, *w2cT2, *adja1, *adja2, *adjc1, *adjc2;
    char *t1T1, *t1T2, *t2q1, *t2q2, *t3T1, *t3T2;
    unsigned* am;
    SYM(acos_, g_acos); SYM(ccos_, g_ccos); SYM(na, g_na); SYM(nc, g_nc);
    SYM(ah, g_ah); SYM(al, g_al); SYM(ch_, g_ch); SYM(cl_, g_cl);
    SYM(ofah, g_ofah); SYM(ofal, g_ofal); SYM(ofch, g_ofch); SYM(ofcl, g_ofcl);
    SYM(wp1h, g_wp1h); SYM(wp1l, g_wp1l); SYM(wp2h, g_wp2h); SYM(wp2l, g_wp2l);
    SYM(hp1, g_hp1); SYM(hp2, g_hp2);
    SYM(t1f, g_t1f); SYM(t2f, g_t2f); SYM(t3f, g_t3f);
    SYM(xqa1, g_xqa1); SYM(xqa2, g_xqa2); SYM(xqc1, g_xqc1); SYM(xqc2, g_xqc2);
    SYM(w1aT1, g_w1aT1); SYM(w1aT2, g_w1aT2); SYM(w2aT1, g_w2aT1); SYM(w2aT2, g_w2aT2);
    SYM(w1cT1, g_w1cT1); SYM(w1cT2, g_w1cT2); SYM(w2cT1, g_w2cT1); SYM(w2cT2, g_w2cT2);
    SYM(adja1, g_adja1); SYM(adja2, g_adja2); SYM(adjc1, g_adjc1); SYM(adjc2, g_adjc2);
    SYM(t1T1, g_t1T1); SYM(t1T2, g_t1T2); SYM(t2q1, g_t2q1); SYM(t2q2, g_t2q2);
    SYM(t3T1, g_t3T1); SYM(t3T2, g_t3T2);
    SYM(am, g_amax);

    // 1: amax init; 2-5: act-path prep; 6: first int8 GEMM (ncu target)
    initamax_k<<<1, 32>>>(am);
    absmax_k<<<256, 256>>>(act, (size_t)BQ * PP * DDA / 4, am + AM_ACT);
    absmax_k<<<128, 256>>>(a_w1, (size_t)DDA * HID / 4, am + AM_W1A);
    quant_k<<<512, 256>>>(act, (size_t)BQ * PP * DDA / 4, am + AM_ACT, xqa1, xqa2);
    transquant_k<<<dim3(DDA / 32, HID / 32, 1), 256>>>(a_w1, DDA, HID, am + AM_W1A, w1aT1, w1aT2);
    gi(xqa1, xqa2, w1aT1, w1aT2, BQ * PP, HID, DDA, 0, 0, 0, 1,
       am + AM_ACT, am + AM_W1A, t1f, 0, 0, HID, 0, 0, 0, 0, am + AM_T1A);

    // remaining prep
    absmax_k<<<512, 256>>>(comp, (size_t)BQ * PP * DDC / 4, am + AM_COMP);
    absmax_k<<<128, 256>>>(a_w2, (size_t)HID * DDA / 4, am + AM_W2A);
    absmax_k<<<256, 256>>>(c_w1, (size_t)DDC * HID / 4, am + AM_W1C);
    absmax_k<<<256, 256>>>(c_w2, (size_t)HID * DDC / 4, am + AM_W2C);
    quant_k<<<1024, 256>>>(comp, (size_t)BQ * PP * DDC / 4, am + AM_COMP, xqc1, xqc2);
    transquant_k<<<dim3(HID / 32, DDA / 32, 1), 256>>>(a_w2, HID, DDA, am + AM_W2A, w2aT1, w2aT2);
    transquant_k<<<dim3(DDC / 32, HID / 32, 1), 256>>>(c_w1, DDC, HID, am + AM_W1C, w1cT1, w1cT2);
    transquant_k<<<dim3(HID / 32, DDC / 32, 1), 256>>>(c_w2, HID, DDC, am + AM_W2C, w2cT1, w2cT2);
    split_k<<<1024, 256>>>(act, ah, al, (size_t)BQ * PP * DDA / 4);
    split_k<<<2048, 256>>>(comp, ch_, cl_, (size_t)BQ * PP * DDC / 4);

    // grams (bf16x3, symmetric) + norms + mirror + graph
    gb(ah, al, ah, al, acos_, PP, PP, DDA, 0, 1,
       (long)PP * DDA, (long)PP * DDA, (long)PP * PP, BQ, PP);
    gb(ch_, cl_, ch_, cl_, ccos_, PP, PP, DDC, 0, 1,
       (long)PP * DDC, (long)PP * DDC, (long)PP * PP, BQ, PP);
    norms_k<<<(BQ * PP + 255) / 256, 256>>>(acos_, na);
    norms_k<<<(BQ * PP + 255) / 256, 256>>>(ccos_, nc);
    mirror_k<<<dim3(32, 32, BQ), 256>>>(acos_, ccos_);
    build_adj_k<<<BQ * PP / 4, 128>>>(iou, dis, acos_, ccos_, na, nc, props,
                                      adja1, adja2, adjc1, adjc2);

    // head weight panels (transposed [128,K])
    zero_k<<<64, 256>>>((uint4*)wp1h, (size_t)DDA * 128 * 2 / 16);
    zero_k<<<64, 256>>>((uint4*)wp1l, (size_t)DDA * 128 * 2 / 16);
    zero_k<<<128, 256>>>((uint4*)wp2h, (size_t)DDC * 128 * 2 / 16);
    zero_k<<<128, 256>>>((uint4*)wp2l, (size_t)DDC * 128 * 2 / 16);
    padsplitT_k<<<128, 256>>>(fa_w, wp1h, wp1l, DDA, 21, 0);
    padsplitT_k<<<256, 256>>>(fc_w, wp2h, wp2l, DDC, 20, 0);
    padsplitT_k<<<512, 256>>>(fr_w, wp2h, wp2l, DDC, 40, 20);

    // ---- Act chain (t1 already computed at launch 6) ----
    transquant_k<<<dim3(PP / 32, HID / 32, BQ), 256>>>(t1f, PP, HID, am + AM_T1A, t1T1, t1T2);
    gi(adja1, adja2, t1T1, t1T2, PP, HID, PP,
       (long)PP * PP, (long)HID * PP, (long)PP * HID, BQ,
       am + AM_ADJ, am + AM_T1A, t2f, 0, 0, HID, a_b1, 0, 0, 1, am + AM_T2A);
    quant_k<<<512, 256>>>(t2f, (size_t)BQ * PP * HID / 4, am + AM_T2A, t2q1, t2q2);
    gi(t2q1, t2q2, w2aT1, w2aT2, BQ * PP, DDA, HID, 0, 0, 0, 1,
       am + AM_T2A, am + AM_W2A, t3f, 0, 0, DDA, 0, 0, 0, 0, am + AM_T3A);
    transquant_k<<<dim3(PP / 32, DDA / 32, BQ), 256>>>(t3f, PP, DDA, am + AM_T3A, t3T1, t3T2);
    gi(adja1, adja2, t3T1, t3T2, PP, DDA, PP,
       (long)PP * PP, (long)DDA * PP, (long)PP * DDA, BQ,
       am + AM_ADJ, am + AM_T3A, 0, ofah, ofal, DDA,
       a_b2, act, (long)PP * DDA, 0, 0);
    gb(ofah, ofal, wp1h, wp1l, hp1, BQ * PP, 128, DDA, 128, 0,
       0, 0, (long)BQ * PP * 128, 1, 128);

    // ---- Comp chain ----
    gi(xqc1, xqc2, w1cT1, w1cT2, BQ * PP, HID, DDC, 0, 0, 0, 1,
       am + AM_COMP, am + AM_W1C, t1f, 0, 0, HID, 0, 0, 0, 0, am + AM_T1C);
    transquant_k<<<dim3(PP / 32, HID / 32, BQ), 256>>>(t1f, PP, HID, am + AM_T1C, t1T1, t1T2);
    gi(adjc1, adjc2, t1T1, t1T2, PP, HID, PP,
       (long)PP * PP, (long)HID * PP, (long)PP * HID, BQ,
       am + AM_ADJ, am + AM_T1C, t2f, 0, 0, HID, c_b1, 0, 0, 1, am + AM_T2C);
    quant_k<<<512, 256>>>(t2f, (size_t)BQ * PP * HID / 4, am + AM_T2C, t2q1, t2q2);
    gi(t2q1, t2q2, w2cT1, w2cT2, BQ * PP, DDC, HID, 0, 0, 0, 1,
       am + AM_T2C, am + AM_W2C, t3f, 0, 0, DDC, 0, 0, 0, 0, am + AM_T3C);
    transquant_k<<<dim3(PP / 32, DDC / 32, BQ), 256>>>(t3f, PP, DDC, am + AM_T3C, t3T1, t3T2);
    gi(adjc1, adjc2, t3T1, t3T2, PP, DDC, PP,
       (long)PP * PP, (long)DDC * PP, (long)PP * DDC, BQ,
       am + AM_ADJ, am + AM_T3C, 0, ofch, ofcl, DDC,
       c_b2, comp, (long)PP * DDC, 0, 0);
    gb(ofch, ofcl, wp2h, wp2l, hp2, BQ * PP, 128, DDC, 384, 0,
       0, 0, (long)BQ * PP * 128, 1, 128);

    // heads -> out
    redheads_k<<<(BQ * PP * 81 + 255) / 256, 256>>>(hp1, hp2, fa_b, fc_b, fr_b, out);
}

// round 11
// speedup vs baseline: 2.9479x; 2.9479x over previous
#include <cuda_runtime.h>
#include <cuda_bf16.h>
#include <math.h>
#include <stdint.h>

#define BQ 4
#define PP 1024
#define DDA 1024
#define DDC 3072
#define HID 512
typedef __nv_bfloat16 bf16;

// ---------------- scratch ----------------
__device__ float g_acos[(size_t)BQ*PP*PP];
__device__ float g_ccos[(size_t)BQ*PP*PP];
__device__ float g_na[BQ*PP];
__device__ float g_nc[BQ*PP];
__device__ bf16 g_ah[(size_t)BQ*PP*DDA], g_al[(size_t)BQ*PP*DDA];
__device__ bf16 g_ch[(size_t)BQ*PP*DDC], g_cl[(size_t)BQ*PP*DDC];
__device__ bf16 g_t2h[(size_t)BQ*PP*HID], g_t2l[(size_t)BQ*PP*HID];
__device__ bf16 g_ofah[(size_t)BQ*PP*DDA], g_ofal[(size_t)BQ*PP*DDA];
__device__ bf16 g_ofch[(size_t)BQ*PP*DDC], g_ofcl[(size_t)BQ*PP*DDC];
__device__ bf16 g_w1ah[DDA*HID], g_w1al[DDA*HID];
__device__ bf16 g_w2ah[HID*DDA], g_w2al[HID*DDA];
__device__ bf16 g_w1ch[DDC*HID], g_w1cl[DDC*HID];
__device__ bf16 g_w2ch[HID*DDC], g_w2cl[HID*DDC];
__device__ bf16 g_wp1h[DDA*128], g_wp1l[DDA*128];
__device__ bf16 g_wp2h[DDC*128], g_wp2l[DDC*128];
__device__ float g_hp1[(size_t)8*BQ*PP*128];
__device__ float g_hp2[(size_t)8*BQ*PP*128];
__device__ float g_kp[(size_t)2*BQ*PP*HID];
__device__ float g_t1f[(size_t)BQ*PP*HID];
__device__ float g_t3f[(size_t)BQ*PP*DDC];
// sparse adjacency: per row (b*P+p) compacted entries
__device__ int   g_sidx[(size_t)BQ*PP*PP ? (size_t)BQ*PP*PP : 1];
__device__ float g_swa[(size_t)BQ*PP*PP];
__device__ float g_swc[(size_t)BQ*PP*PP];
__device__ int   g_scnt[BQ*PP];

// ====================== helpers ======================
__device__ __forceinline__ uint32_t smem_u32(const void* p) {
    uint32_t a;
    asm("{ .reg .u64 t; cvta.to.shared.u64 t, %1; cvt.u32.u64 %0, t; }" : "=r"(a) : "l"(p));
    return a;
}
__device__ __forceinline__ uint32_t pack_bf16x2(float lo_e, float hi_e) {
    uint32_t r;
    asm("cvt.rn.bf16x2.f32 %0, %1, %2;" : "=r"(r) : "f"(hi_e), "f"(lo_e));
    return r;
}
__device__ __forceinline__ void split2(float x, float y, uint32_t& h, uint32_t& l) {
    uint32_t ux = __float_as_uint(x), uy = __float_as_uint(y);
    h = __byte_perm(ux, uy, 0x7632);
    float lx = x - __uint_as_float(ux & 0xFFFF0000u);
    float ly = y - __uint_as_float(uy & 0xFFFF0000u);
    l = pack_bf16x2(lx, ly);
}
__device__ __forceinline__ void ldmx4(uint32_t* r, uint32_t addr) {
    asm volatile("ldmatrix.sync.aligned.m8n8.x4.shared.b16 {%0,%1,%2,%3}, [%4];"
                 : "=r"(r[0]), "=r"(r[1]), "=r"(r[2]), "=r"(r[3]) : "r"(addr));
}
__device__ __forceinline__ void ldmx4t(uint32_t* r, uint32_t addr) {
    asm volatile("ldmatrix.sync.aligned.m8n8.x4.trans.shared.b16 {%0,%1,%2,%3}, [%4];"
                 : "=r"(r[0]), "=r"(r[1]), "=r"(r[2]), "=r"(r[3]) : "r"(addr));
}
__device__ __forceinline__ void mma_bf16(float* c, const uint32_t* a, const uint32_t* b) {
    asm volatile(
        "mma.sync.aligned.m16n8k16.row.col.f32.bf16.bf16.f32 "
        "{%0,%1,%2,%3}, {%4,%5,%6,%7}, {%8,%9}, {%0,%1,%2,%3};"
        : "+f"(c[0]), "+f"(c[1]), "+f"(c[2]), "+f"(c[3])
        : "r"(a[0]), "r"(a[1]), "r"(a[2]), "r"(a[3]), "r"(b[0]), "r"(b[1]));
}
__device__ __forceinline__ void cp16(uint32_t dst, const void* src) {
    asm volatile("cp.async.cg.shared.global [%0], [%1], 16;" :: "r"(dst), "l"(src) : "memory");
}
#define CP_COMMIT() asm volatile("cp.async.commit_group;" ::: "memory")

__device__ __forceinline__ uint32_t ksw(int row, int c) {
    return (uint32_t)(row * 64) + ((uint32_t)(c ^ ((row >> 1) & 3)) << 4);
}

// ====================== bf16x3 GEMM (grams, x@w1, t2@w2, heads) ======================
#define ATILE 8192
#define ASTG  16384
#define SBYTES 32768
#define NSTAGE 3
#define GSMEM (NSTAGE*SBYTES)

template<int TBK>
__global__ __launch_bounds__(256, 2)
void gemmx_k(const bf16* __restrict__ Ah, const bf16* __restrict__ Al,
             const bf16* __restrict__ Bh, const bf16* __restrict__ Bl,
             float* __restrict__ C, bf16* __restrict__ Ch, bf16* __restrict__ Cl,
             int N, int K, int Klen, int symm,
             long sA, long sB, long sC,
             const float* __restrict__ bias,
             const float* __restrict__ resid, long sR,
             int ldc, int relu_flag)
{
    if (!Klen && symm && blockIdx.x < blockIdx.y) return;
    extern __shared__ char sm[];
    uint32_t smb = smem_u32(sm);

    const int tid = threadIdx.x;
    const int lane = tid & 31;
    const int wid = tid >> 5;
    const int wm = (wid >> 2) * 64;
    const int wn = (wid & 3) * 32;

    long bz = blockIdx.z;
    const int bm = blockIdx.y * 128;
    const int nxt = N >> 7;
    int bn, kbase, kslice = 0;
    if (Klen) {
        kslice = (int)blockIdx.x / nxt;
        bn = ((int)blockIdx.x - kslice * nxt) << 7;
        kbase = kslice * Klen;
    } else {
        bn = (int)blockIdx.x << 7;
        kbase = 0;
    }
    const int KL = Klen ? Klen : K;

    const bf16* Ahb = Ah + bz * sA + (size_t)bm * K + kbase;
    const bf16* Alb = Al + bz * sA + (size_t)bm * K + kbase;
    const bf16* Bhb = TBK ? (Bh + bz * sB + (size_t)bn * K + kbase)
                          : (Bh + bz * sB + (size_t)kbase * N + bn);
    const bf16* Blb = TBK ? (Bl + bz * sB + (size_t)bn * K + kbase)
                          : (Bl + bz * sB + (size_t)kbase * N + bn);
    float* Cb = C ? (Klen ? C + (size_t)kslice * sC : C + bz * sC) : (float*)0;
    bf16* Chb = Ch ? Ch + bz * sC : (bf16*)0;
    bf16* Clb = Cl ? Cl + bz * sC : (bf16*)0;
    const float* Rb = resid ? resid + bz * sR : (const float*)0;

    float acc[4][4][4];
#pragma unroll
    for (int i = 0; i < 4; i++)
#pragma unroll
        for (int j = 0; j < 4; j++)
#pragma unroll
            for (int r = 0; r < 4; r++) acc[i][j][r] = 0.f;

    const int nch = KL >> 5;

    auto load_stage = [&](int kt, int s) {
        uint32_t base = smb + (uint32_t)s * SBYTES;
        int k0 = kt << 5;
#pragma unroll
        for (int it = 0; it < 4; it++) {
            int id = it * 256 + tid;
            int hl = id >> 9, rid = id & 511;
            int row = rid >> 2, c = rid & 3;
            cp16(base + hl * ATILE + ksw(row, c),
                 (hl ? Alb : Ahb) + (size_t)row * K + k0 + c * 8);
        }
        if (TBK) {
#pragma unroll
            for (int it = 0; it < 4; it++) {
                int id = it * 256 + tid;
                int hl = id >> 9, rid = id & 511;
                int row = rid >> 2, c = rid & 3;
                cp16(base + ASTG + hl * ATILE + ksw(row, c),
                     (hl ? Blb : Bhb) + (size_t)row * K + k0 + c * 8);
            }
        } else {
#pragma unroll
            for (int it = 0; it < 4; it++) {
                int id = it * 256 + tid;
                int hl = id >> 9, rid = id & 511;
                int k = rid >> 4, c = rid & 15;
                cp16(base + ASTG + hl * ATILE + k * 256 + ((c ^ (k & 7)) << 4),
                     (hl ? Blb : Bhb) + (size_t)(k0 + k) * N + c * 8);
            }
        }
        CP_COMMIT();
    };

    load_stage(0, 0);
    load_stage(1, 1);

    int sc = 0, sl = 2;
    for (int kt = 0; kt < nch; kt++) {
        asm volatile("cp.async.wait_group 1;" ::: "memory");
        __syncthreads();
        if (kt + 2 < nch) {
            load_stage(kt + 2, sl);
            sl = (sl + 1 == NSTAGE) ? 0 : sl + 1;
        } else {
            CP_COMMIT();
        }
        uint32_t aB = smb + (uint32_t)sc * SBYTES;
        uint32_t bB = aB + ASTG;
        sc = (sc + 1 == NSTAGE) ? 0 : sc + 1;

#pragma unroll
        for (int kh = 0; kh < 2; kh++) {
            uint32_t ahi[4][4], alo[4][4];
            {
                int u = kh * 2 + (lane >> 4);
#pragma unroll
                for (int i = 0; i < 4; i++) {
                    int r = wm + (lane & 15) + i * 16;
                    uint32_t ro = ksw(r, u);
                    ldmx4(ahi[i], aB + ro);
                    ldmx4(alo[i], aB + ATILE + ro);
                }
            }
#pragma unroll
            for (int jp = 0; jp < 2; jp++) {
                uint32_t bh2[4], bl2[4];
                if (TBK) {
                    int row = wn + jp * 16 + ((lane >> 4) << 3) + (lane & 7);
                    int u = kh * 2 + ((lane >> 3) & 1);
                    uint32_t ro = ksw(row, u);
                    ldmx4(bh2, bB + ro);
                    ldmx4(bl2, bB + ATILE + ro);
                } else {
                    int k = kh * 16 + ((lane >> 3) & 1) * 8 + (lane & 7);
                    uint32_t kro = (uint32_t)k << 8;
                    int colblk = (wn >> 3) + 2 * jp + (lane >> 4);
                    uint32_t ad = kro + ((uint32_t)(colblk ^ (k & 7)) << 4);
                    ldmx4t(bh2, bB + ad);
                    ldmx4t(bl2, bB + ATILE + ad);
                }
                int j0 = 2 * jp, j1 = 2 * jp + 1;
#pragma unroll
                for (int i = 0; i < 4; i++) {
                    mma_bf16(acc[i][j0], ahi[i], bh2 + 0);
                    mma_bf16(acc[i][j1], ahi[i], bh2 + 2);
                }
#pragma unroll
                for (int i = 0; i < 4; i++) {
                    mma_bf16(acc[i][j0], ahi[i], bl2 + 0);
                    mma_bf16(acc[i][j1], ahi[i], bl2 + 2);
                }
#pragma unroll
                for (int i = 0; i < 4; i++) {
                    mma_bf16(acc[i][j0], alo[i], bh2 + 0);
                    mma_bf16(acc[i][j1], alo[i], bh2 + 2);
                }
            }
        }
    }

#pragma unroll
    for (int i = 0; i < 4; i++) {
        int r0 = bm + wm + i * 16 + (lane >> 2);
        int r1 = r0 + 8;
#pragma unroll
        for (int j = 0; j < 4; j++) {
            int gc = bn + wn + j * 8 + (lane & 3) * 2;
            float2 v0 = make_float2(acc[i][j][0], acc[i][j][1]);
            float2 v1 = make_float2(acc[i][j][2], acc[i][j][3]);
            if (bias) {
                float2 bv = *reinterpret_cast<const float2*>(bias + gc);
                v0.x += bv.x; v0.y += bv.y;
                v1.x += bv.x; v1.y += bv.y;
            }
            if (Rb) {
                float2 q0 = *reinterpret_cast<const float2*>(Rb + (size_t)r0 * ldc + gc);
                float2 q1 = *reinterpret_cast<const float2*>(Rb + (size_t)r1 * ldc + gc);
                v0.x += q0.x; v0.y += q0.y;
                v1.x += q1.x; v1.y += q1.y;
            }
            if (relu_flag) {
                v0.x = fmaxf(v0.x, 0.f); v0.y = fmaxf(v0.y, 0.f);
                v1.x = fmaxf(v1.x, 0.f); v1.y = fmaxf(v1.y, 0.f);
            }
            if (Cb) {
                *reinterpret_cast<float2*>(Cb + (size_t)r0 * ldc + gc) = v0;
                *reinterpret_cast<float2*>(Cb + (size_t)r1 * ldc + gc) = v1;
            }
            if (Chb) {
                uint32_t h0, l0, h1, l1;
                split2(v0.x, v0.y, h0, l0);
                split2(v1.x, v1.y, h1, l1);
                *reinterpret_cast<uint32_t*>(Chb + (size_t)r0 * ldc + gc) = h0;
                *reinterpret_cast<uint32_t*>(Clb + (size_t)r0 * ldc + gc) = l0;
                *reinterpret_cast<uint32_t*>(Chb + (size_t)r1 * ldc + gc) = h1;
                *reinterpret_cast<uint32_t*>(Clb + (size_t)r1 * ldc + gc) = l1;
            }
        }
    }
}

// ====================== sparse adjacency SpMM ======================
// one CTA (256 thr) per output row: out[row,:] = sum_e w[e] * X[b, idx[e], :]
// epilogue: +bias, +resid, relu, write bf16 hi/lo split.
template<int NPT>
__global__ __launch_bounds__(256)
void spmm_k(const int* __restrict__ scnt, const int* __restrict__ sidx,
            const float* __restrict__ swgt, const float* __restrict__ X,
            const float* __restrict__ bias, const float* __restrict__ resid,
            bf16* __restrict__ outH, bf16* __restrict__ outL, int relu_flag)
{
    constexpr int W = NPT * 256;
    __shared__ int s_i[PP];
    __shared__ float s_w[PP];
    int row = blockIdx.x;
    int b = row >> 10;
    int tid = threadIdx.x;
    int cnt = scnt[row];
    const int* ip = sidx + (size_t)row * PP;
    const float* wp = swgt + (size_t)row * PP;
    for (int i = tid; i < cnt; i += 256) { s_i[i] = ip[i]; s_w[i] = wp[i]; }
    __syncthreads();
    const float* Xb = X + (((size_t)b << 10) * W);
    float a0[NPT], a1[NPT], a2[NPT], a3[NPT];
#pragma unroll
    for (int r = 0; r < NPT; r++) { a0[r] = a1[r] = a2[r] = a3[r] = 0.f; }
    int e = 0;
    for (; e + 4 <= cnt; e += 4) {
        const float* x0 = Xb + (size_t)s_i[e + 0] * W;
        const float* x1 = Xb + (size_t)s_i[e + 1] * W;
        const float* x2 = Xb + (size_t)s_i[e + 2] * W;
        const float* x3 = Xb + (size_t)s_i[e + 3] * W;
        float w0 = s_w[e], w1 = s_w[e + 1], w2 = s_w[e + 2], w3 = s_w[e + 3];
#pragma unroll
        for (int r = 0; r < NPT; r++) {
            int c = r * 256 + tid;
            a0[r] += w0 * x0[c];
            a1[r] += w1 * x1[c];
            a2[r] += w2 * x2[c];
            a3[r] += w3 * x3[c];
        }
    }
    for (; e < cnt; e++) {
        const float* x0 = Xb + (size_t)s_i[e] * W;
        float w0 = s_w[e];
#pragma unroll
        for (int r = 0; r < NPT; r++) a0[r] += w0 * x0[r * 256 + tid];
    }
    unsigned short* oh = reinterpret_cast<unsigned short*>(outH) + (size_t)row * W;
    unsigned short* ol = reinterpret_cast<unsigned short*>(outL) + (size_t)row * W;
#pragma unroll
    for (int r = 0; r < NPT; r++) {
        int c = r * 256 + tid;
        float v = (a0[r] + a1[r]) + (a2[r] + a3[r]);
        if (bias) v += bias[c];
        if (resid) v += resid[(size_t)row * W + c];
        if (relu_flag) v = fmaxf(v, 0.f);
        uint32_t u = __float_as_uint(v);
        float lv = v - __uint_as_float(u & 0xFFFF0000u);
        oh[c] = (unsigned short)(u >> 16);
        ol[c] = (unsigned short)(pack_bf16x2(lv, lv) & 0xFFFFu);
    }
}

// ====================== elementwise kernels ======================
__global__ void split_k(const float* __restrict__ s, bf16* __restrict__ h,
                        bf16* __restrict__ l, size_t n4)
{
    for (size_t i = (size_t)blockIdx.x * blockDim.x + threadIdx.x; i < n4;
         i += (size_t)gridDim.x * blockDim.x) {
        float4 v = reinterpret_cast<const float4*>(s)[i];
        uint32_t h0, l0, h1, l1;
        split2(v.x, v.y, h0, l0);
        split2(v.z, v.w, h1, l1);
        reinterpret_cast<uint2*>(h)[i] = make_uint2(h0, h1);
        reinterpret_cast<uint2*>(l)[i] = make_uint2(l0, l1);
    }
}

__global__ void add2_k(const float* __restrict__ p, size_t n4, float* __restrict__ o)
{
    for (size_t i = (size_t)blockIdx.x * blockDim.x + threadIdx.x; i < n4;
         i += (size_t)gridDim.x * blockDim.x) {
        float4 a = reinterpret_cast<const float4*>(p)[i];
        float4 b = reinterpret_cast<const float4*>(p)[n4 + i];
        a.x += b.x; a.y += b.y; a.z += b.z; a.w += b.w;
        reinterpret_cast<float4*>(o)[i] = a;
    }
}

__global__ void zero_k(uint4* __restrict__ p, size_t n16)
{
    for (size_t i = (size_t)blockIdx.x * blockDim.x + threadIdx.x; i < n16;
         i += (size_t)gridDim.x * blockDim.x)
        p[i] = make_uint4(0, 0, 0, 0);
}

__global__ void padsplit_k(const float* __restrict__ src, bf16* __restrict__ h,
                           bf16* __restrict__ l, int K, int Nsrc, int col0)
{
    int total = K * Nsrc;
    for (int i = blockIdx.x * blockDim.x + threadIdx.x; i < total;
         i += gridDim.x * blockDim.x) {
        int k = i / Nsrc, n = i - k * Nsrc;
        float v = src[i];
        uint32_t u = __float_as_uint(v);
        float lv = v - __uint_as_float(u & 0xFFFF0000u);
        size_t d = (size_t)k * 128 + col0 + n;
        reinterpret_cast<unsigned short*>(h)[d] = (unsigned short)(u >> 16);
        reinterpret_cast<unsigned short*>(l)[d] = (unsigned short)(pack_bf16x2(lv, lv) & 0xFFFFu);
    }
}

__global__ void norms_k(const float* __restrict__ G, float* __restrict__ nrm)
{
    int i = blockIdx.x * blockDim.x + threadIdx.x;
    if (i < BQ * PP) {
        int b = i >> 10, p = i & (PP - 1);
        nrm[i] = sqrtf(G[((size_t)b * PP + p) * PP + p]);
    }
}

__global__ __launch_bounds__(256)
void mirror_k(float* __restrict__ A, float* __restrict__ B)
{
    int tj = blockIdx.x, ti = blockIdx.y, b = blockIdx.z;
    if (ti <= tj || (ti >> 2) == (tj >> 2)) return;
    __shared__ float ta[32][33], tb[32][33];
    int tx = threadIdx.x & 31, ty = threadIdx.x >> 5;
    size_t base = (size_t)b * PP * PP;
#pragma unroll
    for (int it = 0; it < 4; it++) {
        int r = ty + it * 8;
        size_t src = base + (size_t)(tj * 32 + r) * PP + ti * 32 + tx;
        ta[r][tx] = A[src];
        tb[r][tx] = B[src];
    }
    __syncthreads();
#pragma unroll
    for (int it = 0; it < 4; it++) {
        int r = ty + it * 8;
        size_t dst = base + (size_t)(ti * 32 + r) * PP + tj * 32 + tx;
        A[dst] = ta[tx][r];
        B[dst] = tb[tx][r];
    }
}

__global__ void redheads_k(const float* __restrict__ hp1, const float* __restrict__ hp2,
                           const float* __restrict__ fab, const float* __restrict__ fcb,
                           const float* __restrict__ frb, float* __restrict__ out)
{
    int i = blockIdx.x * blockDim.x + threadIdx.x;
    int total = BQ * PP * 81;
    if (i >= total) return;
    int row = i / 81, col = i - row * 81;
    float v;
    if (col < 21) {
        v = fab[col];
#pragma unroll
        for (int s = 0; s < 8; s++)
            v += hp1[((size_t)s * BQ * PP + row) * 128 + col];
    } else {
        int c2 = col - 21;
        v = (c2 < 20) ? fcb[c2] : frb[c2 - 20];
#pragma unroll
        for (int s = 0; s < 8; s++)
            v += hp2[((size_t)s * BQ * PP + row) * 128 + c2];
    }
    out[i] = v;
}

// ---------------- graph construction -> compact sparse lists ----------------
__device__ __forceinline__ void warp_argmin(float& v, int& l)
{
#pragma unroll
    for (int off = 16; off; off >>= 1) {
        float ov = __shfl_down_sync(0xffffffffu, v, off);
        int ol = __shfl_down_sync(0xffffffffu, l, off);
        if (ov < v) { v = ov; l = ol; }
    }
    v = __shfl_sync(0xffffffffu, v, 0);
    l = __shfl_sync(0xffffffffu, l, 0);
}
__device__ __forceinline__ void warp_argmax(float& v, int& l)
{
#pragma unroll
    for (int off = 16; off; off >>= 1) {
        float ov = __shfl_down_sync(0xffffffffu, v, off);
        int ol = __shfl_down_sync(0xffffffffu, l, off);
        if (ov > v) { v = ov; l = ol; }
    }
    v = __shfl_sync(0xffffffffu, v, 0);
    l = __shfl_sync(0xffffffffu, l, 0);
}

__global__ __launch_bounds__(128)
void build_adj_k(const float* __restrict__ iou, const float* __restrict__ dis,
                 const float* __restrict__ acos_, const float* __restrict__ ccos_,
                 const float* __restrict__ na, const float* __restrict__ nc,
                 const int* __restrict__ props,
                 int* __restrict__ sidx, float* __restrict__ swa,
                 float* __restrict__ swc, int* __restrict__ scnt)
{
    __shared__ float sio[4][PP];
    int warp = threadIdx.x >> 5, lane = threadIdx.x & 31;
    int row = blockIdx.x * 4 + warp;
    if (row >= BQ * PP) return;
    int b = row >> 10;
    int p = row & (PP - 1);
    const float* iour = iou + (size_t)row * PP;
    const float* disr = dis + (size_t)row * PP;
    const float* ar = acos_ + (size_t)row * PP;
    const float* cr = ccos_ + (size_t)row * PP;
    const float* nab = na + (b << 10);
    const float* ncb = nc + (b << 10);
    float npa = nab[p], npc = ncb[p];
    int pn = props[b];
    bool pv = p < pn;

    float* io_s = sio[warp];
    for (int q = lane; q < PP; q += 32) io_s[q] = iour[q];
    __syncwarp();

    float dv[6]; int di[6];
#pragma unroll
    for (int j = 0; j < 6; j++) { dv[j] = 3.0e38f; di[j] = -1; }
    float sv[2] = {-3.0e38f, -3.0e38f};
    int si2[2] = {-1, -1};

    for (int q = lane; q < PP; q += 32) {
        float io = io_s[q];
        bool ip = io > 0.0f;
        bool qv = q < pn;
        bool v2 = pv && qv;

        float dm = v2 ? (ip ? 2.0f : disr[q]) : 1.0e9f;
        if (dm < dv[5]) {
            dv[5] = dm; di[5] = q;
#pragma unroll
            for (int j = 5; j > 0; j--) {
                if (dv[j] < dv[j - 1]) {
                    float tv = dv[j]; dv[j] = dv[j - 1]; dv[j - 1] = tv;
                    int ti = di[j]; di[j] = di[j - 1]; di[j - 1] = ti;
                }
            }
        }
        float av = ar[q] / (npa * nab[q] + 1e-6f);
        float sm = v2 ? (ip ? 0.0f : (av - (q == p ? 1.0f : 0.0f))) : -1.0e9f;
        if (sm > sv[1]) {
            if (sm > sv[0]) { sv[1] = sv[0]; si2[1] = si2[0]; sv[0] = sm; si2[0] = q; }
            else            { sv[1] = sm; si2[1] = q; }
        }
    }

    int sel[8];
    {
        int ptr = 0;
        for (int k = 0; k < 6; k++) {
            float cv = (ptr < 6) ? dv[ptr] : 3.0e38f;
            int ci = (ptr < 6) ? di[ptr] : -1;
            float v = cv; int l = lane;
            warp_argmin(v, l);
            sel[k] = __shfl_sync(0xffffffffu, ci, l);
            if (lane == l) ptr++;
        }
    }
    {
        int ptr = 0;
        for (int k = 0; k < 2; k++) {
            float cv = (ptr < 2) ? sv[ptr] : -3.0e38f;
            int ci = (ptr < 2) ? si2[ptr] : -1;
            float v = cv; int l = lane;
            warp_argmax(v, l);
            sel[6 + k] = __shfl_sync(0xffffffffu, ci, l);
            if (lane == l) ptr++;
        }
    }
#pragma unroll
    for (int k = 0; k < 8; k++) {
        int q = sel[k];
        bool ok = (q >= 0) && pv && (q < pn) && !(io_s[q] > 0.0f);
        sel[k] = ok ? q : -1;
    }

    unsigned mbits = 0;
    for (int i = 0; i < 32; i++) {
        int q = lane + 32 * i;
        float io = io_s[q];
        bool bit = (q != p) && (io > 0.7f);
#pragma unroll
        for (int k = 0; k < 8; k++) bit |= (sel[k] == q);
        mbits |= (bit ? 1u : 0u) << i;
    }
    int cnt = __popc(mbits);
#pragma unroll
    for (int off = 16; off; off >>= 1) cnt += __shfl_xor_sync(0xffffffffu, cnt, off);
    float inv = 1.0f / ((float)cnt + 1e-6f);

    // compact emission (warp-ballot prefix; deterministic order)
    int* rI = sidx + (size_t)row * PP;
    float* rA = swa + (size_t)row * PP;
    float* rC = swc + (size_t)row * PP;
    int base = 0;
    for (int i = 0; i < 32; i++) {
        int q = lane + 32 * i;
        float m = ((mbits >> i) & 1u) ? inv : 0.0f;
        if (q == p) m += 1.0f;
        bool en = m > 0.f;
        unsigned bal = __ballot_sync(0xffffffffu, en);
        if (en) {
            int pos = base + __popc(bal & ((1u << lane) - 1u));
            float av = ar[q] / (npa * nab[q] + 1e-6f);
            float cv = cr[q] / (npc * ncb[q] + 1e-6f);
            rI[pos] = q;
            rA[pos] = fmaxf(av * m, 0.f);
            rC[pos] = fmaxf(cv * m, 0.f);
        }
        base += __popc(bal);
    }
    if (lane == 0) scnt[row] = base;
}

// ---------------- host ----------------
static void gx(int tbk,
               const bf16* Ah, const bf16* Al, const bf16* Bh, const bf16* Bl,
               float* C, bf16* Ch, bf16* Cl,
               int M, int N, int K, int Klen, int symm,
               long sA, long sB, long sC, int batch,
               const float* bias, const float* resid, long sR,
               int ldc, int relu)
{
    int nxt = N >> 7;
    int gxd = Klen ? nxt * (K / Klen) : nxt;
    dim3 grid(gxd, M / 128, batch);
    if (tbk) {
        cudaFuncSetAttribute(gemmx_k<1>, cudaFuncAttributeMaxDynamicSharedMemorySize, GSMEM);
        gemmx_k<1><<<grid, 256, GSMEM>>>(Ah, Al, Bh, Bl, C, Ch, Cl, N, K, Klen, symm,
                                         sA, sB, sC, bias, resid, sR, ldc, relu);
    } else {
        cudaFuncSetAttribute(gemmx_k<0>, cudaFuncAttributeMaxDynamicSharedMemorySize, GSMEM);
        gemmx_k<0><<<grid, 256, GSMEM>>>(Ah, Al, Bh, Bl, C, Ch, Cl, N, K, Klen, symm,
                                         sA, sB, sC, bias, resid, sR, ldc, relu);
    }
}

#define SYM(var, sym) cudaGetSymbolAddress((void**)&var, sym)

extern "C" void kernel_launch(void* const* d_in, const int* in_sizes, int n_in,
                              void* d_out, int out_size)
{
    const float* act   = (const float*)d_in[0];
    const float* comp  = (const float*)d_in[1];
    const float* iou   = (const float*)d_in[2];
    const float* dis   = (const float*)d_in[3];
    const int*   props = (const int*)d_in[4];
    const float* a_w1  = (const float*)d_in[5];
    const float* a_b1  = (const float*)d_in[6];
    const float* a_w2  = (const float*)d_in[7];
    const float* a_b2  = (const float*)d_in[8];
    const float* c_w1  = (const float*)d_in[9];
    const float* c_b1  = (const float*)d_in[10];
    const float* c_w2  = (const float*)d_in[11];
    const float* c_b2  = (const float*)d_in[12];
    const float* fa_w  = (const float*)d_in[13];
    const float* fa_b  = (const float*)d_in[14];
    const float* fc_w  = (const float*)d_in[15];
    const float* fc_b  = (const float*)d_in[16];
    const float* fr_w  = (const float*)d_in[17];
    const float* fr_b  = (const float*)d_in[18];
    float* out = (float*)d_out;

    float *acos_, *ccos_, *na, *nc, *hp1, *hp2, *kp, *t1f, *t3f, *swa, *swc;
    bf16 *ah, *al, *ch_, *cl_, *t2h, *t2l, *ofah, *ofal, *ofch, *ofcl;
    bf16 *w1ah, *w1al, *w2ah, *w2al, *w1ch, *w1cl, *w2ch, *w2cl;
    bf16 *wp1h, *wp1l, *wp2h, *wp2l;
    int *sidx, *scnt;
    SYM(acos_, g_acos); SYM(ccos_, g_ccos); SYM(na, g_na); SYM(nc, g_nc);
    SYM(ah, g_ah); SYM(al, g_al); SYM(ch_, g_ch); SYM(cl_, g_cl);
    SYM(t2h, g_t2h); SYM(t2l, g_t2l);
    SYM(ofah, g_ofah); SYM(ofal, g_ofal); SYM(ofch, g_ofch); SYM(ofcl, g_ofcl);
    SYM(w1ah, g_w1ah); SYM(w1al, g_w1al); SYM(w2ah, g_w2ah); SYM(w2al, g_w2al);
    SYM(w1ch, g_w1ch); SYM(w1cl, g_w1cl); SYM(w2ch, g_w2ch); SYM(w2cl, g_w2cl);
    SYM(wp1h, g_wp1h); SYM(wp1l, g_wp1l); SYM(wp2h, g_wp2h); SYM(wp2l, g_wp2l);
    SYM(hp1, g_hp1); SYM(hp2, g_hp2); SYM(kp, g_kp);
    SYM(t1f, g_t1f); SYM(t3f, g_t3f);
    SYM(sidx, g_sidx); SYM(swa, g_swa); SYM(swc, g_swc); SYM(scnt, g_scnt);

    // splits
    split_k<<<1024, 256>>>(act, ah, al, (size_t)BQ * PP * DDA / 4);
    split_k<<<2048, 256>>>(comp, ch_, cl_, (size_t)BQ * PP * DDC / 4);
    split_k<<<256, 256>>>(a_w1, w1ah, w1al, (size_t)DDA * HID / 4);
    split_k<<<256, 256>>>(a_w2, w2ah, w2al, (size_t)HID * DDA / 4);
    split_k<<<512, 256>>>(c_w1, w1ch, w1cl, (size_t)DDC * HID / 4);
    split_k<<<512, 256>>>(c_w2, w2ch, w2cl, (size_t)HID * DDC / 4);

    // head weight panels [K,128]
    zero_k<<<64, 256>>>((uint4*)wp1h, (size_t)DDA * 128 * 2 / 16);
    zero_k<<<64, 256>>>((uint4*)wp1l, (size_t)DDA * 128 * 2 / 16);
    zero_k<<<128, 256>>>((uint4*)wp2h, (size_t)DDC * 128 * 2 / 16);
    zero_k<<<128, 256>>>((uint4*)wp2l, (size_t)DDC * 128 * 2 / 16);
    padsplit_k<<<128, 256>>>(fa_w, wp1h, wp1l, DDA, 21, 0);
    padsplit_k<<<256, 256>>>(fc_w, wp2h, wp2l, DDC, 20, 0);
    padsplit_k<<<512, 256>>>(fr_w, wp2h, wp2l, DDC, 40, 20);

    // grams (symmetric) + norms + mirror + sparse graph
    gx(1, ah, al, ah, al, acos_, 0, 0, PP, PP, DDA, 0, 1,
       (long)PP * DDA, (long)PP * DDA, (long)PP * PP, BQ, 0, 0, 0, PP, 0);
    gx(1, ch_, cl_, ch_, cl_, ccos_, 0, 0, PP, PP, DDC, 0, 1,
       (long)PP * DDC, (long)PP * DDC, (long)PP * PP, BQ, 0, 0, 0, PP, 0);
    norms_k<<<(BQ * PP + 255) / 256, 256>>>(acos_, na);
    norms_k<<<(BQ * PP + 255) / 256, 256>>>(ccos_, nc);
    mirror_k<<<dim3(32, 32, BQ), 256>>>(acos_, ccos_);
    build_adj_k<<<BQ * PP / 4, 128>>>(iou, dis, acos_, ccos_, na, nc, props,
                                      sidx, swa, swc, scnt);

    // ---- Act chain ----
    gx(0, ah, al, w1ah, w1al, kp, 0, 0, BQ * PP, HID, DDA, 512, 0,
       0, 0, (long)BQ * PP * HID, 1, 0, 0, 0, HID, 0);
    add2_k<<<2048, 256>>>(kp, (size_t)BQ * PP * HID / 4, t1f);
    spmm_k<2><<<BQ * PP, 256>>>(scnt, sidx, swa, t1f, a_b1, 0, t2h, t2l, 1);
    gx(0, t2h, t2l, w2ah, w2al, t3f, 0, 0, BQ * PP, DDA, HID, 0, 0,
       0, 0, 0, 1, 0, 0, 0, DDA, 0);
    spmm_k<4><<<BQ * PP, 256>>>(scnt, sidx, swa, t3f, a_b2, act, ofah, ofal, 0);
    gx(0, ofah, ofal, wp1h, wp1l, hp1, 0, 0, BQ * PP, 128, DDA, 128, 0,
       0, 0, (long)BQ * PP * 128, 1, 0, 0, 0, 128, 0);

    // ---- Comp chain ----
    gx(0, ch_, cl_, w1ch, w1cl, kp, 0, 0, BQ * PP, HID, DDC, 1536, 0,
       0, 0, (long)BQ * PP * HID, 1, 0, 0, 0, HID, 0);
    add2_k<<<2048, 256>>>(kp, (size_t)BQ * PP * HID / 4, t1f);
    spmm_k<2><<<BQ * PP, 256>>>(scnt, sidx, swc, t1f, c_b1, 0, t2h, t2l, 1);
    gx(0, t2h, t2l, w2ch, w2cl, t3f, 0, 0, BQ * PP, DDC, HID, 0, 0,
       0, 0, 0, 1, 0, 0, 0, DDC, 0);
    spmm_k<12><<<BQ * PP, 256>>>(scnt, sidx, swc, t3f, c_b2, comp, ofch, ofcl, 0);
    gx(0, ofch, ofcl, wp2h, wp2l, hp2, 0, 0, BQ * PP, 128, DDC, 384, 0,
       0, 0, (long)BQ * PP * 128, 1, 0, 0, 0, 128, 0);

    // heads -> out
    redheads_k<<<(BQ * PP * 81 + 255) / 256, 256>>>(hp1, hp2, fa_b, fc_b, fr_b, out);
}

// round 12
// speedup vs baseline: 3.5368x; 1.1998x over previous
#include <cuda_runtime.h>
#include <cuda_fp16.h>
#include <math.h>
#include <stdint.h>

#define BQ 4
#define PP 1024
#define DDA 1024
#define DDC 3072
#define HID 512
typedef __half h16;

// ---------------- scratch ----------------
__device__ float g_acos[(size_t)BQ*PP*PP];
__device__ float g_ccos[(size_t)BQ*PP*PP];
__device__ float g_na[BQ*PP];
__device__ float g_nc[BQ*PP];
__device__ h16 g_ah[(size_t)BQ*PP*DDA], g_al[(size_t)BQ*PP*DDA];
__device__ h16 g_ch[(size_t)BQ*PP*DDC], g_cl[(size_t)BQ*PP*DDC];
__device__ h16 g_t2h[(size_t)BQ*PP*HID], g_t2l[(size_t)BQ*PP*HID];
__device__ h16 g_ofah[(size_t)BQ*PP*DDA], g_ofal[(size_t)BQ*PP*DDA];
__device__ h16 g_ofch[(size_t)BQ*PP*DDC], g_ofcl[(size_t)BQ*PP*DDC];
__device__ h16 g_w1ah[DDA*HID], g_w1al[DDA*HID];
__device__ h16 g_w2ah[HID*DDA], g_w2al[HID*DDA];
__device__ h16 g_w1ch[DDC*HID], g_w1cl[DDC*HID];
__device__ h16 g_w2ch[HID*DDC], g_w2cl[HID*DDC];
__device__ h16 g_wp1h[DDA*128], g_wp1l[DDA*128];
__device__ h16 g_wp2h[DDC*128], g_wp2l[DDC*128];
__device__ float g_hp1[(size_t)8*BQ*PP*128];
__device__ float g_hp2[(size_t)8*BQ*PP*128];
__device__ float g_kp[(size_t)2*BQ*PP*HID];
__device__ float g_t1f[(size_t)BQ*PP*HID];
__device__ float g_t3f[(size_t)BQ*PP*DDC];
__device__ int   g_sidx[(size_t)BQ*PP*PP];
__device__ float g_swa[(size_t)BQ*PP*PP];
__device__ float g_swc[(size_t)BQ*PP*PP];
__device__ int   g_scnt[BQ*PP];

// ====================== helpers ======================
__device__ __forceinline__ uint32_t smem_u32(const void* p) {
    uint32_t a;
    asm("{ .reg .u64 t; cvta.to.shared.u64 t, %1; cvt.u32.u64 %0, t; }" : "=r"(a) : "l"(p));
    return a;
}
// fp16 pair split: hi = rn(x), lo = rn(x - hi); packs two lanes
__device__ __forceinline__ void split2(float x, float y, uint32_t& h, uint32_t& l) {
    __half hx = __float2half_rn(x), hy = __float2half_rn(y);
    float rx = x - __half2float(hx), ry = y - __half2float(hy);
    __half lx = __float2half_rn(rx), ly = __float2half_rn(ry);
    h = (uint32_t)__half_as_ushort(hx) | ((uint32_t)__half_as_ushort(hy) << 16);
    l = (uint32_t)__half_as_ushort(lx) | ((uint32_t)__half_as_ushort(ly) << 16);
}
__device__ __forceinline__ void split1(float x, unsigned short& h, unsigned short& l) {
    __half hx = __float2half_rn(x);
    float rx = x - __half2float(hx);
    h = __half_as_ushort(hx);
    l = __half_as_ushort(__float2half_rn(rx));
}
__device__ __forceinline__ void ldmx4(uint32_t* r, uint32_t addr) {
    asm volatile("ldmatrix.sync.aligned.m8n8.x4.shared.b16 {%0,%1,%2,%3}, [%4];"
                 : "=r"(r[0]), "=r"(r[1]), "=r"(r[2]), "=r"(r[3]) : "r"(addr));
}
__device__ __forceinline__ void ldmx4t(uint32_t* r, uint32_t addr) {
    asm volatile("ldmatrix.sync.aligned.m8n8.x4.trans.shared.b16 {%0,%1,%2,%3}, [%4];"
                 : "=r"(r[0]), "=r"(r[1]), "=r"(r[2]), "=r"(r[3]) : "r"(addr));
}
__device__ __forceinline__ void mma_f16(float* c, const uint32_t* a, const uint32_t* b) {
    asm volatile(
        "mma.sync.aligned.m16n8k16.row.col.f32.f16.f16.f32 "
        "{%0,%1,%2,%3}, {%4,%5,%6,%7}, {%8,%9}, {%0,%1,%2,%3};"
        : "+f"(c[0]), "+f"(c[1]), "+f"(c[2]), "+f"(c[3])
        : "r"(a[0]), "r"(a[1]), "r"(a[2]), "r"(a[3]), "r"(b[0]), "r"(b[1]));
}
__device__ __forceinline__ void cp16(uint32_t dst, const void* src) {
    asm volatile("cp.async.cg.shared.global [%0], [%1], 16;" :: "r"(dst), "l"(src) : "memory");
}
#define CP_COMMIT() asm volatile("cp.async.commit_group;" ::: "memory")

__device__ __forceinline__ uint32_t ksw(int row, int c) {
    return (uint32_t)(row * 64) + ((uint32_t)(c ^ ((row >> 1) & 3)) << 4);
}

// ====================== fp16 pair GEMM ======================
// TERMS=3: hiA*hiB + hiA*loB + loA*hiB. TERMS=2: hiA*hiB + hiA*loB (A-lo skipped).
#define ATILE 8192
#define ASTG  16384
#define SBYTES 32768
#define NSTAGE 3
#define GSMEM (NSTAGE*SBYTES)

template<int TBK, int TERMS>
__global__ __launch_bounds__(256, 2)
void gemmx_k(const h16* __restrict__ Ah, const h16* __restrict__ Al,
             const h16* __restrict__ Bh, const h16* __restrict__ Bl,
             float* __restrict__ C, h16* __restrict__ Ch, h16* __restrict__ Cl,
             int N, int K, int Klen, int symm,
             long sA, long sB, long sC,
             const float* __restrict__ bias,
             const float* __restrict__ resid, long sR,
             int ldc, int relu_flag)
{
    if (!Klen && symm && blockIdx.x < blockIdx.y) return;
    extern __shared__ char sm[];
    uint32_t smb = smem_u32(sm);

    const int tid = threadIdx.x;
    const int lane = tid & 31;
    const int wid = tid >> 5;
    const int wm = (wid >> 2) * 64;
    const int wn = (wid & 3) * 32;

    long bz = blockIdx.z;
    const int bm = blockIdx.y * 128;
    const int nxt = N >> 7;
    int bn, kbase, kslice = 0;
    if (Klen) {
        kslice = (int)blockIdx.x / nxt;
        bn = ((int)blockIdx.x - kslice * nxt) << 7;
        kbase = kslice * Klen;
    } else {
        bn = (int)blockIdx.x << 7;
        kbase = 0;
    }
    const int KL = Klen ? Klen : K;

    const h16* Ahb = Ah + bz * sA + (size_t)bm * K + kbase;
    const h16* Alb = Al + bz * sA + (size_t)bm * K + kbase;
    const h16* Bhb = TBK ? (Bh + bz * sB + (size_t)bn * K + kbase)
                         : (Bh + bz * sB + (size_t)kbase * N + bn);
    const h16* Blb = TBK ? (Bl + bz * sB + (size_t)bn * K + kbase)
                         : (Bl + bz * sB + (size_t)kbase * N + bn);
    float* Cb = C ? (Klen ? C + (size_t)kslice * sC : C + bz * sC) : (float*)0;
    h16* Chb = Ch ? Ch + bz * sC : (h16*)0;
    h16* Clb = Cl ? Cl + bz * sC : (h16*)0;
    const float* Rb = resid ? resid + bz * sR : (const float*)0;

    float acc[4][4][4];
#pragma unroll
    for (int i = 0; i < 4; i++)
#pragma unroll
        for (int j = 0; j < 4; j++)
#pragma unroll
            for (int r = 0; r < 4; r++) acc[i][j][r] = 0.f;

    const int nch = KL >> 5;

    auto load_stage = [&](int kt, int s) {
        uint32_t base = smb + (uint32_t)s * SBYTES;
        int k0 = kt << 5;
#pragma unroll
        for (int it = 0; it < 4; it++) {
            int id = it * 256 + tid;
            int hl = id >> 9, rid = id & 511;
            int row = rid >> 2, c = rid & 3;
            if (TERMS >= 3 || hl == 0)
                cp16(base + hl * ATILE + ksw(row, c),
                     (hl ? Alb : Ahb) + (size_t)row * K + k0 + c * 8);
        }
        if (TBK) {
#pragma unroll
            for (int it = 0; it < 4; it++) {
                int id = it * 256 + tid;
                int hl = id >> 9, rid = id & 511;
                int row = rid >> 2, c = rid & 3;
                cp16(base + ASTG + hl * ATILE + ksw(row, c),
                     (hl ? Blb : Bhb) + (size_t)row * K + k0 + c * 8);
            }
        } else {
#pragma unroll
            for (int it = 0; it < 4; it++) {
                int id = it * 256 + tid;
                int hl = id >> 9, rid = id & 511;
                int k = rid >> 4, c = rid & 15;
                cp16(base + ASTG + hl * ATILE + k * 256 + ((c ^ (k & 7)) << 4),
                     (hl ? Blb : Bhb) + (size_t)(k0 + k) * N + c * 8);
            }
        }
        CP_COMMIT();
    };

    load_stage(0, 0);
    load_stage(1, 1);

    int sc = 0, sl = 2;
    for (int kt = 0; kt < nch; kt++) {
        asm volatile("cp.async.wait_group 1;" ::: "memory");
        __syncthreads();
        if (kt + 2 < nch) {
            load_stage(kt + 2, sl);
            sl = (sl + 1 == NSTAGE) ? 0 : sl + 1;
        } else {
            CP_COMMIT();
        }
        uint32_t aB = smb + (uint32_t)sc * SBYTES;
        uint32_t bB = aB + ASTG;
        sc = (sc + 1 == NSTAGE) ? 0 : sc + 1;

#pragma unroll
        for (int kh = 0; kh < 2; kh++) {
            uint32_t ahi[4][4], alo[4][4];
            {
                int u = kh * 2 + (lane >> 4);
#pragma unroll
                for (int i = 0; i < 4; i++) {
                    int r = wm + (lane & 15) + i * 16;
                    uint32_t ro = ksw(r, u);
                    ldmx4(ahi[i], aB + ro);
                    if (TERMS >= 3) ldmx4(alo[i], aB + ATILE + ro);
                }
            }
#pragma unroll
            for (int jp = 0; jp < 2; jp++) {
                uint32_t bh2[4], bl2[4];
                if (TBK) {
                    int row = wn + jp * 16 + ((lane >> 4) << 3) + (lane & 7);
                    int u = kh * 2 + ((lane >> 3) & 1);
                    uint32_t ro = ksw(row, u);
                    ldmx4(bh2, bB + ro);
                    ldmx4(bl2, bB + ATILE + ro);
                } else {
                    int k = kh * 16 + ((lane >> 3) & 1) * 8 + (lane & 7);
                    uint32_t kro = (uint32_t)k << 8;
                    int colblk = (wn >> 3) + 2 * jp + (lane >> 4);
                    uint32_t ad = kro + ((uint32_t)(colblk ^ (k & 7)) << 4);
                    ldmx4t(bh2, bB + ad);
                    ldmx4t(bl2, bB + ATILE + ad);
                }
                int j0 = 2 * jp, j1 = 2 * jp + 1;
#pragma unroll
                for (int i = 0; i < 4; i++) {
                    mma_f16(acc[i][j0], ahi[i], bh2 + 0);
                    mma_f16(acc[i][j1], ahi[i], bh2 + 2);
                }
#pragma unroll
                for (int i = 0; i < 4; i++) {
                    mma_f16(acc[i][j0], ahi[i], bl2 + 0);
                    mma_f16(acc[i][j1], ahi[i], bl2 + 2);
                }
                if (TERMS >= 3) {
#pragma unroll
                    for (int i = 0; i < 4; i++) {
                        mma_f16(acc[i][j0], alo[i], bh2 + 0);
                        mma_f16(acc[i][j1], alo[i], bh2 + 2);
                    }
                }
            }
        }
    }

#pragma unroll
    for (int i = 0; i < 4; i++) {
        int r0 = bm + wm + i * 16 + (lane >> 2);
        int r1 = r0 + 8;
#pragma unroll
        for (int j = 0; j < 4; j++) {
            int gc = bn + wn + j * 8 + (lane & 3) * 2;
            float2 v0 = make_float2(acc[i][j][0], acc[i][j][1]);
            float2 v1 = make_float2(acc[i][j][2], acc[i][j][3]);
            if (bias) {
                float2 bv = *reinterpret_cast<const float2*>(bias + gc);
                v0.x += bv.x; v0.y += bv.y;
                v1.x += bv.x; v1.y += bv.y;
            }
            if (Rb) {
                float2 q0 = *reinterpret_cast<const float2*>(Rb + (size_t)r0 * ldc + gc);
                float2 q1 = *reinterpret_cast<const float2*>(Rb + (size_t)r1 * ldc + gc);
                v0.x += q0.x; v0.y += q0.y;
                v1.x += q1.x; v1.y += q1.y;
            }
            if (relu_flag) {
                v0.x = fmaxf(v0.x, 0.f); v0.y = fmaxf(v0.y, 0.f);
                v1.x = fmaxf(v1.x, 0.f); v1.y = fmaxf(v1.y, 0.f);
            }
            if (Cb) {
                *reinterpret_cast<float2*>(Cb + (size_t)r0 * ldc + gc) = v0;
                *reinterpret_cast<float2*>(Cb + (size_t)r1 * ldc + gc) = v1;
            }
            if (Chb) {
                uint32_t h0, l0, h1, l1;
                split2(v0.x, v0.y, h0, l0);
                split2(v1.x, v1.y, h1, l1);
                *reinterpret_cast<uint32_t*>(Chb + (size_t)r0 * ldc + gc) = h0;
                *reinterpret_cast<uint32_t*>(Clb + (size_t)r0 * ldc + gc) = l0;
                *reinterpret_cast<uint32_t*>(Chb + (size_t)r1 * ldc + gc) = h1;
                *reinterpret_cast<uint32_t*>(Clb + (size_t)r1 * ldc + gc) = l1;
            }
        }
    }
}

// ====================== sparse adjacency SpMM ======================
template<int NPT>
__global__ __launch_bounds__(256)
void spmm_k(const int* __restrict__ scnt, const int* __restrict__ sidx,
            const float* __restrict__ swgt, const float* __restrict__ X,
            const float* __restrict__ bias, const float* __restrict__ resid,
            h16* __restrict__ outH, h16* __restrict__ outL, int relu_flag)
{
    constexpr int W = NPT * 256;
    __shared__ int s_i[PP];
    __shared__ float s_w[PP];
    int row = blockIdx.x;
    int b = row >> 10;
    int tid = threadIdx.x;
    int cnt = scnt[row];
    const int* ip = sidx + (size_t)row * PP;
    const float* wp = swgt + (size_t)row * PP;
    for (int i = tid; i < cnt; i += 256) { s_i[i] = ip[i]; s_w[i] = wp[i]; }
    __syncthreads();
    const float* Xb = X + (((size_t)b << 10) * W);
    float a0[NPT], a1[NPT], a2[NPT], a3[NPT];
#pragma unroll
    for (int r = 0; r < NPT; r++) { a0[r] = a1[r] = a2[r] = a3[r] = 0.f; }
    int e = 0;
    for (; e + 4 <= cnt; e += 4) {
        const float* x0 = Xb + (size_t)s_i[e + 0] * W;
        const float* x1 = Xb + (size_t)s_i[e + 1] * W;
        const float* x2 = Xb + (size_t)s_i[e + 2] * W;
        const float* x3 = Xb + (size_t)s_i[e + 3] * W;
        float w0 = s_w[e], w1 = s_w[e + 1], w2 = s_w[e + 2], w3 = s_w[e + 3];
#pragma unroll
        for (int r = 0; r < NPT; r++) {
            int c = r * 256 + tid;
            a0[r] += w0 * x0[c];
            a1[r] += w1 * x1[c];
            a2[r] += w2 * x2[c];
            a3[r] += w3 * x3[c];
        }
    }
    for (; e < cnt; e++) {
        const float* x0 = Xb + (size_t)s_i[e] * W;
        float w0 = s_w[e];
#pragma unroll
        for (int r = 0; r < NPT; r++) a0[r] += w0 * x0[r * 256 + tid];
    }
    unsigned short* oh = reinterpret_cast<unsigned short*>(outH) + (size_t)row * W;
    unsigned short* ol = reinterpret_cast<unsigned short*>(outL) + (size_t)row * W;
#pragma unroll
    for (int r = 0; r < NPT; r++) {
        int c = r * 256 + tid;
        float v = (a0[r] + a1[r]) + (a2[r] + a3[r]);
        if (bias) v += bias[c];
        if (resid) v += resid[(size_t)row * W + c];
        if (relu_flag) v = fmaxf(v, 0.f);
        unsigned short hq, lq;
        split1(v, hq, lq);
        oh[c] = hq;
        ol[c] = lq;
    }
}

// ====================== elementwise kernels ======================
__global__ void split_k(const float* __restrict__ s, h16* __restrict__ h,
                        h16* __restrict__ l, size_t n4)
{
    for (size_t i = (size_t)blockIdx.x * blockDim.x + threadIdx.x; i < n4;
         i += (size_t)gridDim.x * blockDim.x) {
        float4 v = reinterpret_cast<const float4*>(s)[i];
        uint32_t h0, l0, h1, l1;
        split2(v.x, v.y, h0, l0);
        split2(v.z, v.w, h1, l1);
        reinterpret_cast<uint2*>(h)[i] = make_uint2(h0, h1);
        reinterpret_cast<uint2*>(l)[i] = make_uint2(l0, l1);
    }
}

__global__ void add2_k(const float* __restrict__ p, size_t n4, float* __restrict__ o)
{
    for (size_t i = (size_t)blockIdx.x * blockDim.x + threadIdx.x; i < n4;
         i += (size_t)gridDim.x * blockDim.x) {
        float4 a = reinterpret_cast<const float4*>(p)[i];
        float4 b = reinterpret_cast<const float4*>(p)[n4 + i];
        a.x += b.x; a.y += b.y; a.z += b.z; a.w += b.w;
        reinterpret_cast<float4*>(o)[i] = a;
    }
}

__global__ void zero_k(uint4* __restrict__ p, size_t n16)
{
    for (size_t i = (size_t)blockIdx.x * blockDim.x + threadIdx.x; i < n16;
         i += (size_t)gridDim.x * blockDim.x)
        p[i] = make_uint4(0, 0, 0, 0);
}

__global__ void padsplit_k(const float* __restrict__ src, h16* __restrict__ h,
                           h16* __restrict__ l, int K, int Nsrc, int col0)
{
    int total = K * Nsrc;
    for (int i = blockIdx.x * blockDim.x + threadIdx.x; i < total;
         i += gridDim.x * blockDim.x) {
        int k = i / Nsrc, n = i - k * Nsrc;
        unsigned short hq, lq;
        split1(src[i], hq, lq);
        size_t d = (size_t)k * 128 + col0 + n;
        reinterpret_cast<unsigned short*>(h)[d] = hq;
        reinterpret_cast<unsigned short*>(l)[d] = lq;
    }
}

__global__ void norms_k(const float* __restrict__ G, float* __restrict__ nrm)
{
    int i = blockIdx.x * blockDim.x + threadIdx.x;
    if (i < BQ * PP) {
        int b = i >> 10, p = i & (PP - 1);
        nrm[i] = sqrtf(G[((size_t)b * PP + p) * PP + p]);
    }
}

__global__ __launch_bounds__(256)
void mirror_k(float* __restrict__ A, float* __restrict__ B)
{
    int tj = blockIdx.x, ti = blockIdx.y, b = blockIdx.z;
    if (ti <= tj || (ti >> 2) == (tj >> 2)) return;
    __shared__ float ta[32][33], tb[32][33];
    int tx = threadIdx.x & 31, ty = threadIdx.x >> 5;
    size_t base = (size_t)b * PP * PP;
#pragma unroll
    for (int it = 0; it < 4; it++) {
        int r = ty + it * 8;
        size_t src = base + (size_t)(tj * 32 + r) * PP + ti * 32 + tx;
        ta[r][tx] = A[src];
        tb[r][tx] = B[src];
    }
    __syncthreads();
#pragma unroll
    for (int it = 0; it < 4; it++) {
        int r = ty + it * 8;
        size_t dst = base + (size_t)(ti * 32 + r) * PP + tj * 32 + tx;
        A[dst] = ta[tx][r];
        B[dst] = tb[tx][r];
    }
}

__global__ void redheads_k(const float* __restrict__ hp1, const float* __restrict__ hp2,
                           const float* __restrict__ fab, const float* __restrict__ fcb,
                           const float* __restrict__ frb, float* __restrict__ out)
{
    int i = blockIdx.x * blockDim.x + threadIdx.x;
    int total = BQ * PP * 81;
    if (i >= total) return;
    int row = i / 81, col = i - row * 81;
    float v;
    if (col < 21) {
        v = fab[col];
#pragma unroll
        for (int s = 0; s < 8; s++)
            v += hp1[((size_t)s * BQ * PP + row) * 128 + col];
    } else {
        int c2 = col - 21;
        v = (c2 < 20) ? fcb[c2] : frb[c2 - 20];
#pragma unroll
        for (int s = 0; s < 8; s++)
            v += hp2[((size_t)s * BQ * PP + row) * 128 + c2];
    }
    out[i] = v;
}

// ---------------- graph construction -> compact sparse lists ----------------
__device__ __forceinline__ void warp_argmin(float& v, int& l)
{
#pragma unroll
    for (int off = 16; off; off >>= 1) {
        float ov = __shfl_down_sync(0xffffffffu, v, off);
        int ol = __shfl_down_sync(0xffffffffu, l, off);
        if (ov < v) { v = ov; l = ol; }
    }
    v = __shfl_sync(0xffffffffu, v, 0);
    l = __shfl_sync(0xffffffffu, l, 0);
}
__device__ __forceinline__ void warp_argmax(float& v, int& l)
{
#pragma unroll
    for (int off = 16; off; off >>= 1) {
        float ov = __shfl_down_sync(0xffffffffu, v, off);
        int ol = __shfl_down_sync(0xffffffffu, l, off);
        if (ov > v) { v = ov; l = ol; }
    }
    v = __shfl_sync(0xffffffffu, v, 0);
    l = __shfl_sync(0xffffffffu, l, 0);
}

__global__ __launch_bounds__(128)
void build_adj_k(const float* __restrict__ iou, const float* __restrict__ dis,
                 const float* __restrict__ acos_, const float* __restrict__ ccos_,
                 const float* __restrict__ na, const float* __restrict__ nc,
                 const int* __restrict__ props,
                 int* __restrict__ sidx, float* __restrict__ swa,
                 float* __restrict__ swc, int* __restrict__ scnt)
{
    __shared__ float sio[4][PP];
    int warp = threadIdx.x >> 5, lane = threadIdx.x & 31;
    int row = blockIdx.x * 4 + warp;
    if (row >= BQ * PP) return;
    int b = row >> 10;
    int p = row & (PP - 1);
    const float* iour = iou + (size_t)row * PP;
    const float* disr = dis + (size_t)row * PP;
    const float* ar = acos_ + (size_t)row * PP;
    const float* cr = ccos_ + (size_t)row * PP;
    const float* nab = na + (b << 10);
    const float* ncb = nc + (b << 10);
    float npa = nab[p], npc = ncb[p];
    int pn = props[b];
    bool pv = p < pn;

    float* io_s = sio[warp];
    for (int q = lane; q < PP; q += 32) io_s[q] = iour[q];
    __syncwarp();

    float dv[6]; int di[6];
#pragma unroll
    for (int j = 0; j < 6; j++) { dv[j] = 3.0e38f; di[j] = -1; }
    float sv[2] = {-3.0e38f, -3.0e38f};
    int si2[2] = {-1, -1};

    for (int q = lane; q < PP; q += 32) {
        float io = io_s[q];
        bool ip = io > 0.0f;
        bool qv = q < pn;
        bool v2 = pv && qv;

        float dm = v2 ? (ip ? 2.0f : disr[q]) : 1.0e9f;
        if (dm < dv[5]) {
            dv[5] = dm; di[5] = q;
#pragma unroll
            for (int j = 5; j > 0; j--) {
                if (dv[j] < dv[j - 1]) {
                    float tv = dv[j]; dv[j] = dv[j - 1]; dv[j - 1] = tv;
                    int ti = di[j]; di[j] = di[j - 1]; di[j - 1] = ti;
                }
            }
        }
        float av = ar[q] / (npa * nab[q] + 1e-6f);
        float sm = v2 ? (ip ? 0.0f : (av - (q == p ? 1.0f : 0.0f))) : -1.0e9f;
        if (sm > sv[1]) {
            if (sm > sv[0]) { sv[1] = sv[0]; si2[1] = si2[0]; sv[0] = sm; si2[0] = q; }
            else            { sv[1] = sm; si2[1] = q; }
        }
    }

    int sel[8];
    {
        int ptr = 0;
        for (int k = 0; k < 6; k++) {
            float cv = (ptr < 6) ? dv[ptr] : 3.0e38f;
            int ci = (ptr < 6) ? di[ptr] : -1;
            float v = cv; int l = lane;
            warp_argmin(v, l);
            sel[k] = __shfl_sync(0xffffffffu, ci, l);
            if (lane == l) ptr++;
        }
    }
    {
        int ptr = 0;
        for (int k = 0; k < 2; k++) {
            float cv = (ptr < 2) ? sv[ptr] : -3.0e38f;
            int ci = (ptr < 2) ? si2[ptr] : -1;
            float v = cv; int l = lane;
            warp_argmax(v, l);
            sel[6 + k] = __shfl_sync(0xffffffffu, ci, l);
            if (lane == l) ptr++;
        }
    }
#pragma unroll
    for (int k = 0; k < 8; k++) {
        int q = sel[k];
        bool ok = (q >= 0) && pv && (q < pn) && !(io_s[q] > 0.0f);
        sel[k] = ok ? q : -1;
    }

    unsigned mbits = 0;
    for (int i = 0; i < 32; i++) {
        int q = lane + 32 * i;
        float io = io_s[q];
        bool bit = (q != p) && (io > 0.7f);
#pragma unroll
        for (int k = 0; k < 8; k++) bit |= (sel[k] == q);
        mbits |= (bit ? 1u : 0u) << i;
    }
    int cnt = __popc(mbits);
#pragma unroll
    for (int off = 16; off; off >>= 1) cnt += __shfl_xor_sync(0xffffffffu, cnt, off);
    float inv = 1.0f / ((float)cnt + 1e-6f);

    int* rI = sidx + (size_t)row * PP;
    float* rA = swa + (size_t)row * PP;
    float* rC = swc + (size_t)row * PP;
    int base = 0;
    for (int i = 0; i < 32; i++) {
        int q = lane + 32 * i;
        float m = ((mbits >> i) & 1u) ? inv : 0.0f;
        if (q == p) m += 1.0f;
        bool en = m > 0.f;
        unsigned bal = __ballot_sync(0xffffffffu, en);
        if (en) {
            int pos = base + __popc(bal & ((1u << lane) - 1u));
            float av = ar[q] / (npa * nab[q] + 1e-6f);
            float cv = cr[q] / (npc * ncb[q] + 1e-6f);
            rI[pos] = q;
            rA[pos] = fmaxf(av * m, 0.f);
            rC[pos] = fmaxf(cv * m, 0.f);
        }
        base += __popc(bal);
    }
    if (lane == 0) scnt[row] = base;
}

// ---------------- host ----------------
static void gx(int tbk, int terms,
               const h16* Ah, const h16* Al, const h16* Bh, const h16* Bl,
               float* C, h16* Ch, h16* Cl,
               int M, int N, int K, int Klen, int symm,
               long sA, long sB, long sC, int batch,
               const float* bias, const float* resid, long sR,
               int ldc, int relu)
{
    int nxt = N >> 7;
    int gxd = Klen ? nxt * (K / Klen) : nxt;
    dim3 grid(gxd, M / 128, batch);
    if (tbk == 1 && terms == 3) {
        cudaFuncSetAttribute(gemmx_k<1,3>, cudaFuncAttributeMaxDynamicSharedMemorySize, GSMEM);
        gemmx_k<1,3><<<grid, 256, GSMEM>>>(Ah, Al, Bh, Bl, C, Ch, Cl, N, K, Klen, symm,
                                           sA, sB, sC, bias, resid, sR, ldc, relu);
    } else if (tbk == 1 && terms == 2) {
        cudaFuncSetAttribute(gemmx_k<1,2>, cudaFuncAttributeMaxDynamicSharedMemorySize, GSMEM);
        gemmx_k<1,2><<<grid, 256, GSMEM>>>(Ah, Al, Bh, Bl, C, Ch, Cl, N, K, Klen, symm,
                                           sA, sB, sC, bias, resid, sR, ldc, relu);
    } else if (tbk == 0 && terms == 2) {
        cudaFuncSetAttribute(gemmx_k<0,2>, cudaFuncAttributeMaxDynamicSharedMemorySize, GSMEM);
        gemmx_k<0,2><<<grid, 256, GSMEM>>>(Ah, Al, Bh, Bl, C, Ch, Cl, N, K, Klen, symm,
                                           sA, sB, sC, bias, resid, sR, ldc, relu);
    } else {
        cudaFuncSetAttribute(gemmx_k<0,3>, cudaFuncAttributeMaxDynamicSharedMemorySize, GSMEM);
        gemmx_k<0,3><<<grid, 256, GSMEM>>>(Ah, Al, Bh, Bl, C, Ch, Cl, N, K, Klen, symm,
                                           sA, sB, sC, bias, resid, sR, ldc, relu);
    }
}

#define SYM(var, sym) cudaGetSymbolAddress((void**)&var, sym)

extern "C" void kernel_launch(void* const* d_in, const int* in_sizes, int n_in,
                              void* d_out, int out_size)
{
    const float* act   = (const float*)d_in[0];
    const float* comp  = (const float*)d_in[1];
    const float* iou   = (const float*)d_in[2];
    const float* dis   = (const float*)d_in[3];
    const int*   props = (const int*)d_in[4];
    const float* a_w1  = (const float*)d_in[5];
    const float* a_b1  = (const float*)d_in[6];
    const float* a_w2  = (const float*)d_in[7];
    const float* a_b2  = (const float*)d_in[8];
    const float* c_w1  = (const float*)d_in[9];
    const float* c_b1  = (const float*)d_in[10];
    const float* c_w2  = (const float*)d_in[11];
    const float* c_b2  = (const float*)d_in[12];
    const float* fa_w  = (const float*)d_in[13];
    const float* fa_b  = (const float*)d_in[14];
    const float* fc_w  = (const float*)d_in[15];
    const float* fc_b  = (const float*)d_in[16];
    const float* fr_w  = (const float*)d_in[17];
    const float* fr_b  = (const float*)d_in[18];
    float* out = (float*)d_out;

    float *acos_, *ccos_, *na, *nc, *hp1, *hp2, *kp, *t1f, *t3f, *swa, *swc;
    h16 *ah, *al, *ch_, *cl_, *t2h, *t2l, *ofah, *ofal, *ofch, *ofcl;
    h16 *w1ah, *w1al, *w2ah, *w2al, *w1ch, *w1cl, *w2ch, *w2cl;
    h16 *wp1h, *wp1l, *wp2h, *wp2l;
    int *sidx, *scnt;
    SYM(acos_, g_acos); SYM(ccos_, g_ccos); SYM(na, g_na); SYM(nc, g_nc);
    SYM(ah, g_ah); SYM(al, g_al); SYM(ch_, g_ch); SYM(cl_, g_cl);
    SYM(t2h, g_t2h); SYM(t2l, g_t2l);
    SYM(ofah, g_ofah); SYM(ofal, g_ofal); SYM(ofch, g_ofch); SYM(ofcl, g_ofcl);
    SYM(w1ah, g_w1ah); SYM(w1al, g_w1al); SYM(w2ah, g_w2ah); SYM(w2al, g_w2al);
    SYM(w1ch, g_w1ch); SYM(w1cl, g_w1cl); SYM(w2ch, g_w2ch); SYM(w2cl, g_w2cl);
    SYM(wp1h, g_wp1h); SYM(wp1l, g_wp1l); SYM(wp2h, g_wp2h); SYM(wp2l, g_wp2l);
    SYM(hp1, g_hp1); SYM(hp2, g_hp2); SYM(kp, g_kp);
    SYM(t1f, g_t1f); SYM(t3f, g_t3f);
    SYM(sidx, g_sidx); SYM(swa, g_swa); SYM(swc, g_swc); SYM(scnt, g_scnt);

    // splits (fp16 pairs)
    split_k<<<1024, 256>>>(act, ah, al, (size_t)BQ * PP * DDA / 4);
    split_k<<<2048, 256>>>(comp, ch_, cl_, (size_t)BQ * PP * DDC / 4);
    split_k<<<256, 256>>>(a_w1, w1ah, w1al, (size_t)DDA * HID / 4);
    split_k<<<256, 256>>>(a_w2, w2ah, w2al, (size_t)HID * DDA / 4);
    split_k<<<512, 256>>>(c_w1, w1ch, w1cl, (size_t)DDC * HID / 4);
    split_k<<<512, 256>>>(c_w2, w2ch, w2cl, (size_t)HID * DDC / 4);

    // head weight panels [K,128]
    zero_k<<<64, 256>>>((uint4*)wp1h, (size_t)DDA * 128 * 2 / 16);
    zero_k<<<64, 256>>>((uint4*)wp1l, (size_t)DDA * 128 * 2 / 16);
    zero_k<<<128, 256>>>((uint4*)wp2h, (size_t)DDC * 128 * 2 / 16);
    zero_k<<<128, 256>>>((uint4*)wp2l, (size_t)DDC * 128 * 2 / 16);
    padsplit_k<<<128, 256>>>(fa_w, wp1h, wp1l, DDA, 21, 0);
    padsplit_k<<<256, 256>>>(fc_w, wp2h, wp2l, DDC, 20, 0);
    padsplit_k<<<512, 256>>>(fr_w, wp2h, wp2l, DDC, 40, 20);

    // grams: act fp16x3 (feeds top-k selection), comp fp16x2 (weights only)
    gx(1, 3, ah, al, ah, al, acos_, 0, 0, PP, PP, DDA, 0, 1,
       (long)PP * DDA, (long)PP * DDA, (long)PP * PP, BQ, 0, 0, 0, PP, 0);
    gx(1, 2, ch_, cl_, ch_, cl_, ccos_, 0, 0, PP, PP, DDC, 0, 1,
       (long)PP * DDC, (long)PP * DDC, (long)PP * PP, BQ, 0, 0, 0, PP, 0);
    norms_k<<<(BQ * PP + 255) / 256, 256>>>(acos_, na);
    norms_k<<<(BQ * PP + 255) / 256, 256>>>(ccos_, nc);
    mirror_k<<<dim3(32, 32, BQ), 256>>>(acos_, ccos_);
    build_adj_k<<<BQ * PP / 4, 128>>>(iou, dis, acos_, ccos_, na, nc, props,
                                      sidx, swa, swc, scnt);

    // ---- Act chain (fp16x2 GEMMs + SpMM) ----
    gx(0, 2, ah, al, w1ah, w1al, kp, 0, 0, BQ * PP, HID, DDA, 512, 0,
       0, 0, (long)BQ * PP * HID, 1, 0, 0, 0, HID, 0);
    add2_k<<<2048, 256>>>(kp, (size_t)BQ * PP * HID / 4, t1f);
    spmm_k<2><<<BQ * PP, 256>>>(scnt, sidx, swa, t1f, a_b1, 0, t2h, t2l, 1);
    gx(0, 2, t2h, t2l, w2ah, w2al, t3f, 0, 0, BQ * PP, DDA, HID, 0, 0,
       0, 0, 0, 1, 0, 0, 0, DDA, 0);
    spmm_k<4><<<BQ * PP, 256>>>(scnt, sidx, swa, t3f, a_b2, act, ofah, ofal, 0);
    gx(0, 3, ofah, ofal, wp1h, wp1l, hp1, 0, 0, BQ * PP, 128, DDA, 128, 0,
       0, 0, (long)BQ * PP * 128, 1, 0, 0, 0, 128, 0);

    // ---- Comp chain ----
    gx(0, 2, ch_, cl_, w1ch, w1cl, kp, 0, 0, BQ * PP, HID, DDC, 1536, 0,
       0, 0, (long)BQ * PP * HID, 1, 0, 0, 0, HID, 0);
    add2_k<<<2048, 256>>>(kp, (size_t)BQ * PP * HID / 4, t1f);
    spmm_k<2><<<BQ * PP, 256>>>(scnt, sidx, swc, t1f, c_b1, 0, t2h, t2l, 1);
    gx(0, 2, t2h, t2l, w2ch, w2cl, t3f, 0, 0, BQ * PP, DDC, HID, 0, 0,
       0, 0, 0, 1, 0, 0, 0, DDC, 0);
    spmm_k<12><<<BQ * PP, 256>>>(scnt, sidx, swc, t3f, c_b2, comp, ofch, ofcl, 0);
    gx(0, 3, ofch, ofcl, wp2h, wp2l, hp2, 0, 0, BQ * PP, 128, DDC, 384, 0,
       0, 0, (long)BQ * PP * 128, 1, 0, 0, 0, 128, 0);

    // heads -> out
    redheads_k<<<(BQ * PP * 81 + 255) / 256, 256>>>(hp1, hp2, fa_b, fc_b, fr_b, out);
}